// round 10
// baseline (speedup 1.0000x reference)
#include <cuda_runtime.h>
#include <cstdint>

#define BATCH 8
#define CCH   256
#define NTOK  1024
#define HEADS 8
#define HD    32

// -------- scratch --------
__device__ float g_qkv[3ull * BATCH * CCH * NTOK];   // [w][b][c][n], tf32-rounded
__device__ float g_attn[(size_t)BATCH * CCH * NTOK]; // [b][c][n], tf32-rounded
__device__ float g_xr[(size_t)BATCH * CCH * NTOK];   // tf32-rounded x
__device__ float g_wr[4ull * CCH * CCH];             // tf32 Wq*qsc, Wk, Wv, Wo
__device__ float g_bias[4 * CCH];                    // bq*qsc, bk, bv, bo

// log2(e)/sqrt(32): folded into Wq/bq so attention scores land in exp2 domain
#define QSC 0.2550348942479215f

__device__ __forceinline__ uint32_t f2tf32(float x) {
    uint32_t r;
    asm("cvt.rna.tf32.f32 %0, %1;" : "=r"(r) : "f"(x));
    return r;
}

// exp2 via FMA pipe only: magic-number round, deg-4 poly, exponent add on bits.
__device__ __forceinline__ float fexp2(float z) {
    const float MAGIC = 12582912.0f;          // 2^23 + 2^22
    float m  = z + MAGIC;
    float nf = m - MAGIC;
    float f  = z - nf;                        // [-0.5, 0.5]
    float p = 9.618129e-3f;
    p = fmaf(p, f, 5.550411e-2f);
    p = fmaf(p, f, 2.4022651e-1f);
    p = fmaf(p, f, 6.9314718e-1f);
    p = fmaf(p, f, 1.0f);
    return __int_as_float(__float_as_int(p) + (__float_as_int(m) << 23));
}

__device__ __forceinline__ void mma8(float* d, const uint32_t* a, uint32_t b0, uint32_t b1) {
    asm volatile("mma.sync.aligned.m16n8k8.row.col.f32.tf32.tf32.f32 "
        "{%0,%1,%2,%3}, {%4,%5,%6,%7}, {%8,%9}, {%0,%1,%2,%3};"
        : "+f"(d[0]), "+f"(d[1]), "+f"(d[2]), "+f"(d[3])
        : "r"(a[0]), "r"(a[1]), "r"(a[2]), "r"(a[3]), "r"(b0), "r"(b1));
}

// ============================================================================
// Pre-round: tf32-round x and 4 weights (Wq pre-scaled by QSC).
// ============================================================================
#define NX4 (BATCH * CCH * NTOK / 4)   // 524288
#define NW4 (CCH * CCH / 4)            // 16384

__global__ void __launch_bounds__(256) preround_kernel(
    const float* __restrict__ x,
    const float* __restrict__ Wq, const float* __restrict__ Wk,
    const float* __restrict__ Wv, const float* __restrict__ Wo)
{
    int i = blockIdx.x * 256 + threadIdx.x;
    float scale = 1.0f;
    const float4* src;
    float4* dst;
    if (i < NX4) {
        src = (const float4*)x + i;
        dst = (float4*)g_xr + i;
    } else {
        int j = i - NX4;
        int which = j >> 14;
        int k = j & (NW4 - 1);
        const float* W = (which == 0) ? Wq : (which == 1) ? Wk : (which == 2) ? Wv : Wo;
        if (which == 0) scale = QSC;
        src = (const float4*)W + k;
        dst = (float4*)(g_wr + (size_t)which * CCH * CCH) + k;
    }
    float4 v = *src;
    uint4 o;
    o.x = f2tf32(v.x * scale); o.y = f2tf32(v.y * scale);
    o.z = f2tf32(v.z * scale); o.w = f2tf32(v.w * scale);
    *(uint4*)dst = o;
}

__global__ void __launch_bounds__(256) bias_copy_kernel(
    const float* __restrict__ bq, const float* __restrict__ bk,
    const float* __restrict__ bv, const float* __restrict__ bo)
{
    int i = threadIdx.x + blockIdx.x * 256;
    if (i < CCH)          g_bias[i] = bq[i] * QSC;
    else if (i < 2 * CCH) g_bias[i] = bk[i - CCH];
    else if (i < 3 * CCH) g_bias[i] = bv[i - 2 * CCH];
    else if (i < 4 * CCH) g_bias[i] = bo[i - 3 * CCH];
}

// ============================================================================
// GEMM body: pre-rounded inputs, raw float4 staging, prefetch pipeline.
// Block tile 128(o) x 128(n), 8 warps 4x2, warp tile 32x64, BK=32.
// round_out: qkv stores tf32-rounded so attention stages/loads raw bits.
// ============================================================================
#define WSTR 36
#define XSTR 132

__device__ __forceinline__ void proj_body(
    const float* __restrict__ W, const float* __restrict__ bias,
    const float* __restrict__ Xb, float* __restrict__ Yb,
    const float* __restrict__ Rb, int o0, int n0, int round_out,
    float* Ws, float* Xs)
{
    const int t = threadIdx.x, lane = t & 31, w = t >> 5;
    const int qg = lane >> 2, p = lane & 3;
    const int r0  = (w >> 1) * 32;
    const int n0w = (w & 1) * 64;

    const int wo = t >> 3, wc4 = t & 7;
    const int xc = t >> 5, xj4 = t & 31;

    const uint32_t* Wu = (const uint32_t*)Ws;
    const uint32_t* Xu = (const uint32_t*)Xs;

    float acc[2][8][4];
    #pragma unroll
    for (int mt = 0; mt < 2; mt++)
        #pragma unroll
        for (int nt = 0; nt < 8; nt++)
            #pragma unroll
            for (int k = 0; k < 4; k++) acc[mt][nt][k] = 0.f;

    float4 wf[4], xf[4];
    #pragma unroll
    for (int r = 0; r < 4; r++) {
        wf[r] = *(const float4*)&W[(size_t)(o0 + wo + r * 32) * CCH + wc4 * 4];
        xf[r] = *(const float4*)&Xb[(size_t)(xc + r * 8) * NTOK + n0 + xj4 * 4];
    }

    for (int k0 = 0; k0 < CCH; k0 += 32) {
        #pragma unroll
        for (int r = 0; r < 4; r++) {
            *(float4*)&Ws[(wo + r * 32) * WSTR + wc4 * 4] = wf[r];
            *(float4*)&Xs[(xc + r * 8) * XSTR + xj4 * 4] = xf[r];
        }
        __syncthreads();

        if (k0 + 32 < CCH) {
            const int kn = k0 + 32;
            #pragma unroll
            for (int r = 0; r < 4; r++) {
                wf[r] = *(const float4*)&W[(size_t)(o0 + wo + r * 32) * CCH + kn + wc4 * 4];
                xf[r] = *(const float4*)&Xb[(size_t)(kn + xc + r * 8) * NTOK + n0 + xj4 * 4];
            }
        }

        #pragma unroll
        for (int s = 0; s < 4; s++) {
            uint32_t a[2][4];
            #pragma unroll
            for (int mt = 0; mt < 2; mt++) {
                int rr = r0 + mt * 16 + qg;
                a[mt][0] = Wu[rr * WSTR + 8 * s + p];
                a[mt][1] = Wu[(rr + 8) * WSTR + 8 * s + p];
                a[mt][2] = Wu[rr * WSTR + 8 * s + p + 4];
                a[mt][3] = Wu[(rr + 8) * WSTR + 8 * s + p + 4];
            }
            #pragma unroll
            for (int nt = 0; nt < 8; nt++) {
                uint32_t b0 = Xu[(8 * s + p) * XSTR + n0w + nt * 8 + qg];
                uint32_t b1 = Xu[(8 * s + p + 4) * XSTR + n0w + nt * 8 + qg];
                mma8(acc[0][nt], a[0], b0, b1);
                mma8(acc[1][nt], a[1], b0, b1);
            }
        }
        __syncthreads();
    }

    #pragma unroll
    for (int mt = 0; mt < 2; mt++) {
        int rr = r0 + mt * 16 + qg;
        int oa = o0 + rr;
        float bb0 = bias[oa], bb8 = bias[oa + 8];
        #pragma unroll
        for (int nt = 0; nt < 8; nt++) {
            int col = n0 + n0w + nt * 8 + 2 * p;
            size_t i0 = (size_t)oa * NTOK + col;
            size_t i8 = (size_t)(oa + 8) * NTOK + col;
            float2 v0 = make_float2(acc[mt][nt][0] + bb0, acc[mt][nt][1] + bb0);
            float2 v8 = make_float2(acc[mt][nt][2] + bb8, acc[mt][nt][3] + bb8);
            if (Rb) {
                float2 r0v = *(const float2*)&Rb[i0];
                float2 r8v = *(const float2*)&Rb[i8];
                v0.x += r0v.x; v0.y += r0v.y;
                v8.x += r8v.x; v8.y += r8v.y;
            }
            if (round_out) {
                v0.x = __uint_as_float(f2tf32(v0.x));
                v0.y = __uint_as_float(f2tf32(v0.y));
                v8.x = __uint_as_float(f2tf32(v8.x));
                v8.y = __uint_as_float(f2tf32(v8.y));
            }
            *(float2*)&Yb[i0] = v0;
            *(float2*)&Yb[i8] = v8;
        }
    }
}

// Fused Q/K/V projection: grid.y in [0,6) = which*2 + o-tile(128).
__global__ void __launch_bounds__(256) qkv_mma_kernel()
{
    __shared__ float Ws[128 * WSTR];
    __shared__ float Xs[32 * XSTR];

    const int b     = blockIdx.z;
    const int which = blockIdx.y >> 1;
    const int o0    = (blockIdx.y & 1) * 128;
    const int n0    = blockIdx.x * 128;

    const float* W  = g_wr + (size_t)which * CCH * CCH;
    const float* Xb = g_xr + (size_t)b * CCH * NTOK;
    float* Yb = g_qkv + ((size_t)which * BATCH + b) * CCH * NTOK;

    proj_body(W, g_bias + which * CCH, Xb, Yb, nullptr, o0, n0, 1, Ws, Xs);
}

// Output projection (+residual): full precision output.
__global__ void __launch_bounds__(256) oproj_mma_kernel(
    float* __restrict__ out, const float* __restrict__ x)
{
    __shared__ float Ws[128 * WSTR];
    __shared__ float Xs[32 * XSTR];

    const int b  = blockIdx.z;
    const int o0 = blockIdx.y * 128;
    const int n0 = blockIdx.x * 128;

    const float* W  = g_wr + 3ull * CCH * CCH;
    const float* Xb = g_attn + (size_t)b * CCH * NTOK;
    const float* Rb = x + (size_t)b * CCH * NTOK;
    float* Yb = out + (size_t)b * CCH * NTOK;

    proj_body(W, g_bias + 3 * CCH, Xb, Yb, Rb, o0, n0, 0, Ws, Xs);
}

// ============================================================================
// Attention v5: 128-thread CTAs (4 warps x 32 rows, q-tile 128) for wave
// balance (grid 512, 4 CTAs/SM). All inputs pre-rounded tf32 -> staging and
// Q-fragment loads are raw bit copies. Key-permutation MMA2, exp2 magic-round,
// P fed as truncated fp32, double-buffered K/V.
// ============================================================================
#define KSTR 36

__global__ void __launch_bounds__(128, 4) attn_mma_kernel()
{
    __shared__ uint32_t Ku[2][32 * KSTR];
    __shared__ uint32_t Vu[2][32 * KSTR];

    const int t = threadIdx.x, w = t >> 5, lane = t & 31;
    const int qg = lane >> 2, p = lane & 3;
    const int b = blockIdx.z, h = blockIdx.y, q0 = blockIdx.x * 128;

    const size_t ho = ((size_t)b * CCH + h * HD) * NTOK;
    const float* Q = g_qkv + ho;                              // pre-scaled by QSC
    const float* K = g_qkv + (size_t)BATCH * CCH * NTOK + ho;
    const float* V = g_qkv + 2ull * BATCH * CCH * NTOK + ho;
    float* O = g_attn + ho;

    // ---- Q A-fragments: raw bit loads (already tf32 + scaled) ----
    const int rbase = q0 + w * 32 + qg;
    uint32_t aq[2][4][4];
    #pragma unroll
    for (int mt = 0; mt < 2; mt++)
        #pragma unroll
        for (int s = 0; s < 4; s++) {
            int r = rbase + mt * 16;
            const uint32_t* Qa = (const uint32_t*)Q + (size_t)(8 * s + p) * NTOK;
            const uint32_t* Qb = (const uint32_t*)Q + (size_t)(8 * s + p + 4) * NTOK;
            aq[mt][s][0] = Qa[r];
            aq[mt][s][1] = Qa[r + 8];
            aq[mt][s][2] = Qb[r];
            aq[mt][s][3] = Qb[r + 8];
        }

    float oc[2][4][4];
    #pragma unroll
    for (int mt = 0; mt < 2; mt++)
        #pragma unroll
        for (int nt = 0; nt < 4; nt++)
            #pragma unroll
            for (int k = 0; k < 4; k++) oc[mt][nt][k] = 0.f;
    float rs[2][2] = {{0.f, 0.f}, {0.f, 0.f}};

    // staging map: 128 threads cover 32x32 via 8 iters each of K and V
    const int jj = t & 31, d0 = t >> 5;      // d0 in 0..3, rows d0 + 4*it
    uint32_t kf[8], vf[8];
    #pragma unroll
    for (int it = 0; it < 8; it++) {
        kf[it] = ((const uint32_t*)K)[(size_t)(d0 + it * 4) * NTOK + jj];
        vf[it] = ((const uint32_t*)V)[(size_t)(d0 + it * 4) * NTOK + jj];
    }

    for (int c = 0; c < 32; c++) {
        const int cur = c & 1;
        uint32_t* Kc = Ku[cur];
        uint32_t* Vc = Vu[cur];

        #pragma unroll
        for (int it = 0; it < 8; it++) {
            Kc[(d0 + it * 4) * KSTR + jj] = kf[it];
            Vc[(d0 + it * 4) * KSTR + jj] = vf[it];
        }
        __syncthreads();

        if (c < 31) {
            const int kt = (c + 1) * 32;
            #pragma unroll
            for (int it = 0; it < 8; it++) {
                kf[it] = ((const uint32_t*)K)[(size_t)(d0 + it * 4) * NTOK + kt + jj];
                vf[it] = ((const uint32_t*)V)[(size_t)(d0 + it * 4) * NTOK + kt + jj];
            }
        }

        // ---- MMA1: S(log2 domain) = Q K^T ----
        float sc[2][4][4];
        #pragma unroll
        for (int mt = 0; mt < 2; mt++)
            #pragma unroll
            for (int nt = 0; nt < 4; nt++)
                #pragma unroll
                for (int k = 0; k < 4; k++) sc[mt][nt][k] = 0.f;

        #pragma unroll
        for (int nt = 0; nt < 4; nt++)
            #pragma unroll
            for (int s = 0; s < 4; s++) {
                uint32_t b0 = Kc[(8 * s + p) * KSTR + nt * 8 + qg];
                uint32_t b1 = Kc[(8 * s + p + 4) * KSTR + nt * 8 + qg];
                mma8(sc[0][nt], aq[0][s], b0, b1);
                mma8(sc[1][nt], aq[1][s], b0, b1);
            }

        // ---- exp2 in place + rowsum partials ----
        #pragma unroll
        for (int mt = 0; mt < 2; mt++)
            #pragma unroll
            for (int nt = 0; nt < 4; nt++) {
                float e0 = fexp2(sc[mt][nt][0]);
                float e1 = fexp2(sc[mt][nt][1]);
                float e2 = fexp2(sc[mt][nt][2]);
                float e3 = fexp2(sc[mt][nt][3]);
                rs[mt][0] += e0 + e1;
                rs[mt][1] += e2 + e3;
                sc[mt][nt][0] = e0; sc[mt][nt][1] = e1;
                sc[mt][nt][2] = e2; sc[mt][nt][3] = e3;
            }

        // ---- MMA2: O += P V^T, sigma=[0,2,4,6,1,3,5,7], P as raw fp32 bits ----
        #pragma unroll
        for (int s = 0; s < 4; s++) {
            uint32_t ap[2][4];
            #pragma unroll
            for (int mt = 0; mt < 2; mt++) {
                ap[mt][0] = __float_as_uint(sc[mt][s][0]);
                ap[mt][1] = __float_as_uint(sc[mt][s][2]);
                ap[mt][2] = __float_as_uint(sc[mt][s][1]);
                ap[mt][3] = __float_as_uint(sc[mt][s][3]);
            }
            #pragma unroll
            for (int nt = 0; nt < 4; nt++) {
                uint2 bv = *(const uint2*)&Vc[(nt * 8 + qg) * KSTR + 8 * s + 2 * p];
                mma8(oc[0][nt], ap[0], bv.x, bv.y);
                mma8(oc[1][nt], ap[1], bv.x, bv.y);
            }
        }
    }

    // ---- normalize + store O tf32-rounded ----
    #pragma unroll
    for (int mt = 0; mt < 2; mt++) {
        float s0 = rs[mt][0], s1 = rs[mt][1];
        s0 += __shfl_xor_sync(0xffffffffu, s0, 1);
        s0 += __shfl_xor_sync(0xffffffffu, s0, 2);
        s1 += __shfl_xor_sync(0xffffffffu, s1, 1);
        s1 += __shfl_xor_sync(0xffffffffu, s1, 2);
        float r0i = 1.0f / s0, r1i = 1.0f / s1;
        int r = rbase + mt * 16;
        #pragma unroll
        for (int nt = 0; nt < 4; nt++) {
            float* Oa = O + (size_t)(nt * 8 + 2 * p) * NTOK;
            float* Ob = O + (size_t)(nt * 8 + 2 * p + 1) * NTOK;
            Oa[r]     = __uint_as_float(f2tf32(oc[mt][nt][0] * r0i));
            Ob[r]     = __uint_as_float(f2tf32(oc[mt][nt][1] * r0i));
            Oa[r + 8] = __uint_as_float(f2tf32(oc[mt][nt][2] * r1i));
            Ob[r + 8] = __uint_as_float(f2tf32(oc[mt][nt][3] * r1i));
        }
    }
}

// ============================================================================
extern "C" void kernel_launch(void* const* d_in, const int* in_sizes, int n_in,
                              void* d_out, int out_size)
{
    const float* x  = (const float*)d_in[0];
    const float* Wq = (const float*)d_in[1];
    const float* bq = (const float*)d_in[2];
    const float* Wk = (const float*)d_in[3];
    const float* bk = (const float*)d_in[4];
    const float* Wv = (const float*)d_in[5];
    const float* bv = (const float*)d_in[6];
    const float* Wo = (const float*)d_in[7];
    const float* bo = (const float*)d_in[8];
    float* out = (float*)d_out;

    bias_copy_kernel<<<(4 * CCH + 255) / 256, 256>>>(bq, bk, bv, bo);
    preround_kernel<<<(NX4 + 4 * NW4 + 255) / 256, 256>>>(x, Wq, Wk, Wv, Wo);

    qkv_mma_kernel<<<dim3(NTOK / 128, 6, BATCH), 256>>>();
    attn_mma_kernel<<<dim3(NTOK / 128, HEADS, BATCH), 128>>>();
    oproj_mma_kernel<<<dim3(NTOK / 128, CCH / 128, BATCH), 256>>>(out, x);
}

// round 11
// speedup vs baseline: 1.0835x; 1.0835x over previous
#include <cuda_runtime.h>
#include <cstdint>

#define BATCH 8
#define CCH   256
#define NTOK  1024
#define HEADS 8
#define HD    32

// -------- scratch --------
__device__ float g_qkv[3ull * BATCH * CCH * NTOK];   // [w][b][c][n], tf32-rounded
__device__ float g_attn[(size_t)BATCH * CCH * NTOK]; // [b][c][n], tf32-rounded
__device__ float g_xr[(size_t)BATCH * CCH * NTOK];   // tf32-rounded x
__device__ float g_wr[4ull * CCH * CCH];             // tf32 Wq*qsc, Wk, Wv, Wo
__device__ float g_bias[4 * CCH];                    // bq*qsc, bk, bv, bo

// log2(e)/sqrt(32): folded into Wq/bq so attention scores land in exp2 domain
#define QSC 0.2550348942479215f

__device__ __forceinline__ uint32_t f2tf32(float x) {
    uint32_t r;
    asm("cvt.rna.tf32.f32 %0, %1;" : "=r"(r) : "f"(x));
    return r;
}

// exp2 via MUFU.EX2: single issue slot, runs on the otherwise-idle MUFU pipe
// (rt_SMSP=8 -> 16 lanes/cyc/SM; all 67M exps = ~16us chip-wide, fully hidden).
__device__ __forceinline__ float fexp2(float z) {
    float r;
    asm("ex2.approx.f32 %0, %1;" : "=f"(r) : "f"(z));
    return r;
}

__device__ __forceinline__ void mma8(float* d, const uint32_t* a, uint32_t b0, uint32_t b1) {
    asm volatile("mma.sync.aligned.m16n8k8.row.col.f32.tf32.tf32.f32 "
        "{%0,%1,%2,%3}, {%4,%5,%6,%7}, {%8,%9}, {%0,%1,%2,%3};"
        : "+f"(d[0]), "+f"(d[1]), "+f"(d[2]), "+f"(d[3])
        : "r"(a[0]), "r"(a[1]), "r"(a[2]), "r"(a[3]), "r"(b0), "r"(b1));
}

// ============================================================================
// Pre-round: tf32-round x and 4 weights (Wq pre-scaled by QSC).
// ============================================================================
#define NX4 (BATCH * CCH * NTOK / 4)   // 524288
#define NW4 (CCH * CCH / 4)            // 16384

__global__ void __launch_bounds__(256) preround_kernel(
    const float* __restrict__ x,
    const float* __restrict__ Wq, const float* __restrict__ Wk,
    const float* __restrict__ Wv, const float* __restrict__ Wo)
{
    int i = blockIdx.x * 256 + threadIdx.x;
    float scale = 1.0f;
    const float4* src;
    float4* dst;
    if (i < NX4) {
        src = (const float4*)x + i;
        dst = (float4*)g_xr + i;
    } else {
        int j = i - NX4;
        int which = j >> 14;
        int k = j & (NW4 - 1);
        const float* W = (which == 0) ? Wq : (which == 1) ? Wk : (which == 2) ? Wv : Wo;
        if (which == 0) scale = QSC;
        src = (const float4*)W + k;
        dst = (float4*)(g_wr + (size_t)which * CCH * CCH) + k;
    }
    float4 v = *src;
    uint4 o;
    o.x = f2tf32(v.x * scale); o.y = f2tf32(v.y * scale);
    o.z = f2tf32(v.z * scale); o.w = f2tf32(v.w * scale);
    *(uint4*)dst = o;
}

__global__ void __launch_bounds__(256) bias_copy_kernel(
    const float* __restrict__ bq, const float* __restrict__ bk,
    const float* __restrict__ bv, const float* __restrict__ bo)
{
    int i = threadIdx.x + blockIdx.x * 256;
    if (i < CCH)          g_bias[i] = bq[i] * QSC;
    else if (i < 2 * CCH) g_bias[i] = bk[i - CCH];
    else if (i < 3 * CCH) g_bias[i] = bv[i - 2 * CCH];
    else if (i < 4 * CCH) g_bias[i] = bo[i - 3 * CCH];
}

// ============================================================================
// GEMM body: pre-rounded inputs, raw float4 staging, prefetch pipeline.
// Block tile 128(o) x 128(n), 8 warps 4x2, warp tile 32x64, BK=32.
// ============================================================================
#define WSTR 36
#define XSTR 132

__device__ __forceinline__ void proj_body(
    const float* __restrict__ W, const float* __restrict__ bias,
    const float* __restrict__ Xb, float* __restrict__ Yb,
    const float* __restrict__ Rb, int o0, int n0, int round_out,
    float* Ws, float* Xs)
{
    const int t = threadIdx.x, lane = t & 31, w = t >> 5;
    const int qg = lane >> 2, p = lane & 3;
    const int r0  = (w >> 1) * 32;
    const int n0w = (w & 1) * 64;

    const int wo = t >> 3, wc4 = t & 7;
    const int xc = t >> 5, xj4 = t & 31;

    const uint32_t* Wu = (const uint32_t*)Ws;
    const uint32_t* Xu = (const uint32_t*)Xs;

    float acc[2][8][4];
    #pragma unroll
    for (int mt = 0; mt < 2; mt++)
        #pragma unroll
        for (int nt = 0; nt < 8; nt++)
            #pragma unroll
            for (int k = 0; k < 4; k++) acc[mt][nt][k] = 0.f;

    float4 wf[4], xf[4];
    #pragma unroll
    for (int r = 0; r < 4; r++) {
        wf[r] = *(const float4*)&W[(size_t)(o0 + wo + r * 32) * CCH + wc4 * 4];
        xf[r] = *(const float4*)&Xb[(size_t)(xc + r * 8) * NTOK + n0 + xj4 * 4];
    }

    for (int k0 = 0; k0 < CCH; k0 += 32) {
        #pragma unroll
        for (int r = 0; r < 4; r++) {
            *(float4*)&Ws[(wo + r * 32) * WSTR + wc4 * 4] = wf[r];
            *(float4*)&Xs[(xc + r * 8) * XSTR + xj4 * 4] = xf[r];
        }
        __syncthreads();

        if (k0 + 32 < CCH) {
            const int kn = k0 + 32;
            #pragma unroll
            for (int r = 0; r < 4; r++) {
                wf[r] = *(const float4*)&W[(size_t)(o0 + wo + r * 32) * CCH + kn + wc4 * 4];
                xf[r] = *(const float4*)&Xb[(size_t)(kn + xc + r * 8) * NTOK + n0 + xj4 * 4];
            }
        }

        #pragma unroll
        for (int s = 0; s < 4; s++) {
            uint32_t a[2][4];
            #pragma unroll
            for (int mt = 0; mt < 2; mt++) {
                int rr = r0 + mt * 16 + qg;
                a[mt][0] = Wu[rr * WSTR + 8 * s + p];
                a[mt][1] = Wu[(rr + 8) * WSTR + 8 * s + p];
                a[mt][2] = Wu[rr * WSTR + 8 * s + p + 4];
                a[mt][3] = Wu[(rr + 8) * WSTR + 8 * s + p + 4];
            }
            #pragma unroll
            for (int nt = 0; nt < 8; nt++) {
                uint32_t b0 = Xu[(8 * s + p) * XSTR + n0w + nt * 8 + qg];
                uint32_t b1 = Xu[(8 * s + p + 4) * XSTR + n0w + nt * 8 + qg];
                mma8(acc[0][nt], a[0], b0, b1);
                mma8(acc[1][nt], a[1], b0, b1);
            }
        }
        __syncthreads();
    }

    #pragma unroll
    for (int mt = 0; mt < 2; mt++) {
        int rr = r0 + mt * 16 + qg;
        int oa = o0 + rr;
        float bb0 = bias[oa], bb8 = bias[oa + 8];
        #pragma unroll
        for (int nt = 0; nt < 8; nt++) {
            int col = n0 + n0w + nt * 8 + 2 * p;
            size_t i0 = (size_t)oa * NTOK + col;
            size_t i8 = (size_t)(oa + 8) * NTOK + col;
            float2 v0 = make_float2(acc[mt][nt][0] + bb0, acc[mt][nt][1] + bb0);
            float2 v8 = make_float2(acc[mt][nt][2] + bb8, acc[mt][nt][3] + bb8);
            if (Rb) {
                float2 r0v = *(const float2*)&Rb[i0];
                float2 r8v = *(const float2*)&Rb[i8];
                v0.x += r0v.x; v0.y += r0v.y;
                v8.x += r8v.x; v8.y += r8v.y;
            }
            if (round_out) {
                v0.x = __uint_as_float(f2tf32(v0.x));
                v0.y = __uint_as_float(f2tf32(v0.y));
                v8.x = __uint_as_float(f2tf32(v8.x));
                v8.y = __uint_as_float(f2tf32(v8.y));
            }
            *(float2*)&Yb[i0] = v0;
            *(float2*)&Yb[i8] = v8;
        }
    }
}

// Fused Q/K/V projection: grid.y in [0,6) = which*2 + o-tile(128).
__global__ void __launch_bounds__(256) qkv_mma_kernel()
{
    __shared__ float Ws[128 * WSTR];
    __shared__ float Xs[32 * XSTR];

    const int b     = blockIdx.z;
    const int which = blockIdx.y >> 1;
    const int o0    = (blockIdx.y & 1) * 128;
    const int n0    = blockIdx.x * 128;

    const float* W  = g_wr + (size_t)which * CCH * CCH;
    const float* Xb = g_xr + (size_t)b * CCH * NTOK;
    float* Yb = g_qkv + ((size_t)which * BATCH + b) * CCH * NTOK;

    proj_body(W, g_bias + which * CCH, Xb, Yb, nullptr, o0, n0, 1, Ws, Xs);
}

// Output projection (+residual): full precision output.
__global__ void __launch_bounds__(256) oproj_mma_kernel(
    float* __restrict__ out, const float* __restrict__ x)
{
    __shared__ float Ws[128 * WSTR];
    __shared__ float Xs[32 * XSTR];

    const int b  = blockIdx.z;
    const int o0 = blockIdx.y * 128;
    const int n0 = blockIdx.x * 128;

    const float* W  = g_wr + 3ull * CCH * CCH;
    const float* Xb = g_attn + (size_t)b * CCH * NTOK;
    const float* Rb = x + (size_t)b * CCH * NTOK;
    float* Yb = out + (size_t)b * CCH * NTOK;

    proj_body(W, g_bias + 3 * CCH, Xb, Yb, Rb, o0, n0, 0, Ws, Xs);
}

// ============================================================================
// Attention v6: identical to v5 except exp2 now goes through MUFU.EX2,
// removing ~256 FMA-pipe issue slots per warp-chunk (the measured binder).
// ============================================================================
#define KSTR 36

__global__ void __launch_bounds__(128, 4) attn_mma_kernel()
{
    __shared__ uint32_t Ku[2][32 * KSTR];
    __shared__ uint32_t Vu[2][32 * KSTR];

    const int t = threadIdx.x, w = t >> 5, lane = t & 31;
    const int qg = lane >> 2, p = lane & 3;
    const int b = blockIdx.z, h = blockIdx.y, q0 = blockIdx.x * 128;

    const size_t ho = ((size_t)b * CCH + h * HD) * NTOK;
    const float* Q = g_qkv + ho;                              // pre-scaled by QSC
    const float* K = g_qkv + (size_t)BATCH * CCH * NTOK + ho;
    const float* V = g_qkv + 2ull * BATCH * CCH * NTOK + ho;
    float* O = g_attn + ho;

    // ---- Q A-fragments: raw bit loads (already tf32 + scaled) ----
    const int rbase = q0 + w * 32 + qg;
    uint32_t aq[2][4][4];
    #pragma unroll
    for (int mt = 0; mt < 2; mt++)
        #pragma unroll
        for (int s = 0; s < 4; s++) {
            int r = rbase + mt * 16;
            const uint32_t* Qa = (const uint32_t*)Q + (size_t)(8 * s + p) * NTOK;
            const uint32_t* Qb = (const uint32_t*)Q + (size_t)(8 * s + p + 4) * NTOK;
            aq[mt][s][0] = Qa[r];
            aq[mt][s][1] = Qa[r + 8];
            aq[mt][s][2] = Qb[r];
            aq[mt][s][3] = Qb[r + 8];
        }

    float oc[2][4][4];
    #pragma unroll
    for (int mt = 0; mt < 2; mt++)
        #pragma unroll
        for (int nt = 0; nt < 4; nt++)
            #pragma unroll
            for (int k = 0; k < 4; k++) oc[mt][nt][k] = 0.f;
    float rs[2][2] = {{0.f, 0.f}, {0.f, 0.f}};

    const int jj = t & 31, d0 = t >> 5;      // d0 in 0..3, rows d0 + 4*it
    uint32_t kf[8], vf[8];
    #pragma unroll
    for (int it = 0; it < 8; it++) {
        kf[it] = ((const uint32_t*)K)[(size_t)(d0 + it * 4) * NTOK + jj];
        vf[it] = ((const uint32_t*)V)[(size_t)(d0 + it * 4) * NTOK + jj];
    }

    for (int c = 0; c < 32; c++) {
        const int cur = c & 1;
        uint32_t* Kc = Ku[cur];
        uint32_t* Vc = Vu[cur];

        #pragma unroll
        for (int it = 0; it < 8; it++) {
            Kc[(d0 + it * 4) * KSTR + jj] = kf[it];
            Vc[(d0 + it * 4) * KSTR + jj] = vf[it];
        }
        __syncthreads();

        if (c < 31) {
            const int kt = (c + 1) * 32;
            #pragma unroll
            for (int it = 0; it < 8; it++) {
                kf[it] = ((const uint32_t*)K)[(size_t)(d0 + it * 4) * NTOK + kt + jj];
                vf[it] = ((const uint32_t*)V)[(size_t)(d0 + it * 4) * NTOK + kt + jj];
            }
        }

        // ---- MMA1: S(log2 domain) = Q K^T ----
        float sc[2][4][4];
        #pragma unroll
        for (int mt = 0; mt < 2; mt++)
            #pragma unroll
            for (int nt = 0; nt < 4; nt++)
                #pragma unroll
                for (int k = 0; k < 4; k++) sc[mt][nt][k] = 0.f;

        #pragma unroll
        for (int nt = 0; nt < 4; nt++)
            #pragma unroll
            for (int s = 0; s < 4; s++) {
                uint32_t b0 = Kc[(8 * s + p) * KSTR + nt * 8 + qg];
                uint32_t b1 = Kc[(8 * s + p + 4) * KSTR + nt * 8 + qg];
                mma8(sc[0][nt], aq[0][s], b0, b1);
                mma8(sc[1][nt], aq[1][s], b0, b1);
            }

        // ---- exp2 via MUFU + rowsum partials ----
        #pragma unroll
        for (int mt = 0; mt < 2; mt++)
            #pragma unroll
            for (int nt = 0; nt < 4; nt++) {
                float e0 = fexp2(sc[mt][nt][0]);
                float e1 = fexp2(sc[mt][nt][1]);
                float e2 = fexp2(sc[mt][nt][2]);
                float e3 = fexp2(sc[mt][nt][3]);
                rs[mt][0] += e0 + e1;
                rs[mt][1] += e2 + e3;
                sc[mt][nt][0] = e0; sc[mt][nt][1] = e1;
                sc[mt][nt][2] = e2; sc[mt][nt][3] = e3;
            }

        // ---- MMA2: O += P V^T, sigma=[0,2,4,6,1,3,5,7], P as raw fp32 bits ----
        #pragma unroll
        for (int s = 0; s < 4; s++) {
            uint32_t ap[2][4];
            #pragma unroll
            for (int mt = 0; mt < 2; mt++) {
                ap[mt][0] = __float_as_uint(sc[mt][s][0]);
                ap[mt][1] = __float_as_uint(sc[mt][s][2]);
                ap[mt][2] = __float_as_uint(sc[mt][s][1]);
                ap[mt][3] = __float_as_uint(sc[mt][s][3]);
            }
            #pragma unroll
            for (int nt = 0; nt < 4; nt++) {
                uint2 bv = *(const uint2*)&Vc[(nt * 8 + qg) * KSTR + 8 * s + 2 * p];
                mma8(oc[0][nt], ap[0], bv.x, bv.y);
                mma8(oc[1][nt], ap[1], bv.x, bv.y);
            }
        }
    }

    // ---- normalize + store O tf32-rounded ----
    #pragma unroll
    for (int mt = 0; mt < 2; mt++) {
        float s0 = rs[mt][0], s1 = rs[mt][1];
        s0 += __shfl_xor_sync(0xffffffffu, s0, 1);
        s0 += __shfl_xor_sync(0xffffffffu, s0, 2);
        s1 += __shfl_xor_sync(0xffffffffu, s1, 1);
        s1 += __shfl_xor_sync(0xffffffffu, s1, 2);
        float r0i = 1.0f / s0, r1i = 1.0f / s1;
        int r = rbase + mt * 16;
        #pragma unroll
        for (int nt = 0; nt < 4; nt++) {
            float* Oa = O + (size_t)(nt * 8 + 2 * p) * NTOK;
            float* Ob = O + (size_t)(nt * 8 + 2 * p + 1) * NTOK;
            Oa[r]     = __uint_as_float(f2tf32(oc[mt][nt][0] * r0i));
            Ob[r]     = __uint_as_float(f2tf32(oc[mt][nt][1] * r0i));
            Oa[r + 8] = __uint_as_float(f2tf32(oc[mt][nt][2] * r1i));
            Ob[r + 8] = __uint_as_float(f2tf32(oc[mt][nt][3] * r1i));
        }
    }
}

// ============================================================================
extern "C" void kernel_launch(void* const* d_in, const int* in_sizes, int n_in,
                              void* d_out, int out_size)
{
    const float* x  = (const float*)d_in[0];
    const float* Wq = (const float*)d_in[1];
    const float* bq = (const float*)d_in[2];
    const float* Wk = (const float*)d_in[3];
    const float* bk = (const float*)d_in[4];
    const float* Wv = (const float*)d_in[5];
    const float* bv = (const float*)d_in[6];
    const float* Wo = (const float*)d_in[7];
    const float* bo = (const float*)d_in[8];
    float* out = (float*)d_out;

    bias_copy_kernel<<<(4 * CCH + 255) / 256, 256>>>(bq, bk, bv, bo);
    preround_kernel<<<(NX4 + 4 * NW4 + 255) / 256, 256>>>(x, Wq, Wk, Wv, Wo);

    qkv_mma_kernel<<<dim3(NTOK / 128, 6, BATCH), 256>>>();
    attn_mma_kernel<<<dim3(NTOK / 128, HEADS, BATCH), 128>>>();
    oproj_mma_kernel<<<dim3(NTOK / 128, CCH / 128, BATCH), 256>>>(out, x);
}

// round 12
// speedup vs baseline: 1.2934x; 1.1937x over previous
#include <cuda_runtime.h>
#include <cuda_fp16.h>
#include <cstdint>

#define BATCH 8
#define CCH   256
#define NTOK  1024
#define HEADS 8
#define HD    32

// -------- scratch --------
__device__ __half g_qkvh[3ull * BATCH * CCH * NTOK]; // fp16 Q(pre-scaled),K,V [w][b][c][n]
__device__ float g_attn[(size_t)BATCH * CCH * NTOK]; // [b][c][n], tf32-rounded
__device__ float g_xr[(size_t)BATCH * CCH * NTOK];   // tf32-rounded x
__device__ float g_wr[4ull * CCH * CCH];             // tf32 Wq*qsc, Wk, Wv, Wo
__device__ float g_bias[4 * CCH];                    // bq*qsc, bk, bv, bo

// log2(e)/sqrt(32): folded into Wq/bq so attention scores land in exp2 domain
#define QSC 0.2550348942479215f

__device__ __forceinline__ uint32_t f2tf32(float x) {
    uint32_t r;
    asm("cvt.rna.tf32.f32 %0, %1;" : "=r"(r) : "f"(x));
    return r;
}
__device__ __forceinline__ float fexp2(float z) {
    float r;
    asm("ex2.approx.f32 %0, %1;" : "=f"(r) : "f"(z));
    return r;
}
// pack two fp32 -> f16x2 {lo, hi}
__device__ __forceinline__ uint32_t pack2(float lo, float hi) {
    uint32_t d;
    asm("cvt.rn.f16x2.f32 %0, %1, %2;" : "=r"(d) : "f"(hi), "f"(lo));
    return d;
}
__device__ __forceinline__ uint32_t prmt(uint32_t a, uint32_t b, uint32_t sel) {
    uint32_t d;
    asm("prmt.b32 %0, %1, %2, %3;" : "=r"(d) : "r"(a), "r"(b), "r"(sel));
    return d;
}

__device__ __forceinline__ void mma8(float* d, const uint32_t* a, uint32_t b0, uint32_t b1) {
    asm volatile("mma.sync.aligned.m16n8k8.row.col.f32.tf32.tf32.f32 "
        "{%0,%1,%2,%3}, {%4,%5,%6,%7}, {%8,%9}, {%0,%1,%2,%3};"
        : "+f"(d[0]), "+f"(d[1]), "+f"(d[2]), "+f"(d[3])
        : "r"(a[0]), "r"(a[1]), "r"(a[2]), "r"(a[3]), "r"(b0), "r"(b1));
}
__device__ __forceinline__ void mma16(float* d, const uint32_t* a, uint32_t b0, uint32_t b1) {
    asm volatile("mma.sync.aligned.m16n8k16.row.col.f32.f16.f16.f32 "
        "{%0,%1,%2,%3}, {%4,%5,%6,%7}, {%8,%9}, {%0,%1,%2,%3};"
        : "+f"(d[0]), "+f"(d[1]), "+f"(d[2]), "+f"(d[3])
        : "r"(a[0]), "r"(a[1]), "r"(a[2]), "r"(a[3]), "r"(b0), "r"(b1));
}

// ============================================================================
// Pre-round: tf32-round x and 4 weights (Wq pre-scaled by QSC).
// ============================================================================
#define NX4 (BATCH * CCH * NTOK / 4)
#define NW4 (CCH * CCH / 4)

__global__ void __launch_bounds__(256) preround_kernel(
    const float* __restrict__ x,
    const float* __restrict__ Wq, const float* __restrict__ Wk,
    const float* __restrict__ Wv, const float* __restrict__ Wo)
{
    int i = blockIdx.x * 256 + threadIdx.x;
    float scale = 1.0f;
    const float4* src;
    float4* dst;
    if (i < NX4) {
        src = (const float4*)x + i;
        dst = (float4*)g_xr + i;
    } else {
        int j = i - NX4;
        int which = j >> 14;
        int k = j & (NW4 - 1);
        const float* W = (which == 0) ? Wq : (which == 1) ? Wk : (which == 2) ? Wv : Wo;
        if (which == 0) scale = QSC;
        src = (const float4*)W + k;
        dst = (float4*)(g_wr + (size_t)which * CCH * CCH) + k;
    }
    float4 v = *src;
    uint4 o;
    o.x = f2tf32(v.x * scale); o.y = f2tf32(v.y * scale);
    o.z = f2tf32(v.z * scale); o.w = f2tf32(v.w * scale);
    *(uint4*)dst = o;
}

__global__ void __launch_bounds__(256) bias_copy_kernel(
    const float* __restrict__ bq, const float* __restrict__ bk,
    const float* __restrict__ bv, const float* __restrict__ bo)
{
    int i = threadIdx.x + blockIdx.x * 256;
    if (i < CCH)          g_bias[i] = bq[i] * QSC;
    else if (i < 2 * CCH) g_bias[i] = bk[i - CCH];
    else if (i < 3 * CCH) g_bias[i] = bv[i - 2 * CCH];
    else if (i < 4 * CCH) g_bias[i] = bo[i - 3 * CCH];
}

// ============================================================================
// GEMM body (tf32): pre-rounded inputs, raw float4 staging, prefetch pipeline.
// Block tile 128x128, 8 warps 4x2, warp tile 32x64. Yh!=null -> fp16 output.
// ============================================================================
#define WSTR 36
#define XSTR 132

__device__ __forceinline__ void proj_body(
    const float* __restrict__ W, const float* __restrict__ bias,
    const float* __restrict__ Xb, float* __restrict__ Yb,
    __half* __restrict__ Yh,
    const float* __restrict__ Rb, int o0, int n0,
    float* Ws, float* Xs)
{
    const int t = threadIdx.x, lane = t & 31, w = t >> 5;
    const int qg = lane >> 2, p = lane & 3;
    const int r0  = (w >> 1) * 32;
    const int n0w = (w & 1) * 64;

    const int wo = t >> 3, wc4 = t & 7;
    const int xc = t >> 5, xj4 = t & 31;

    const uint32_t* Wu = (const uint32_t*)Ws;
    const uint32_t* Xu = (const uint32_t*)Xs;

    float acc[2][8][4];
    #pragma unroll
    for (int mt = 0; mt < 2; mt++)
        #pragma unroll
        for (int nt = 0; nt < 8; nt++)
            #pragma unroll
            for (int k = 0; k < 4; k++) acc[mt][nt][k] = 0.f;

    float4 wf[4], xf[4];
    #pragma unroll
    for (int r = 0; r < 4; r++) {
        wf[r] = *(const float4*)&W[(size_t)(o0 + wo + r * 32) * CCH + wc4 * 4];
        xf[r] = *(const float4*)&Xb[(size_t)(xc + r * 8) * NTOK + n0 + xj4 * 4];
    }

    for (int k0 = 0; k0 < CCH; k0 += 32) {
        #pragma unroll
        for (int r = 0; r < 4; r++) {
            *(float4*)&Ws[(wo + r * 32) * WSTR + wc4 * 4] = wf[r];
            *(float4*)&Xs[(xc + r * 8) * XSTR + xj4 * 4] = xf[r];
        }
        __syncthreads();

        if (k0 + 32 < CCH) {
            const int kn = k0 + 32;
            #pragma unroll
            for (int r = 0; r < 4; r++) {
                wf[r] = *(const float4*)&W[(size_t)(o0 + wo + r * 32) * CCH + kn + wc4 * 4];
                xf[r] = *(const float4*)&Xb[(size_t)(kn + xc + r * 8) * NTOK + n0 + xj4 * 4];
            }
        }

        #pragma unroll
        for (int s = 0; s < 4; s++) {
            uint32_t a[2][4];
            #pragma unroll
            for (int mt = 0; mt < 2; mt++) {
                int rr = r0 + mt * 16 + qg;
                a[mt][0] = Wu[rr * WSTR + 8 * s + p];
                a[mt][1] = Wu[(rr + 8) * WSTR + 8 * s + p];
                a[mt][2] = Wu[rr * WSTR + 8 * s + p + 4];
                a[mt][3] = Wu[(rr + 8) * WSTR + 8 * s + p + 4];
            }
            #pragma unroll
            for (int nt = 0; nt < 8; nt++) {
                uint32_t b0 = Xu[(8 * s + p) * XSTR + n0w + nt * 8 + qg];
                uint32_t b1 = Xu[(8 * s + p + 4) * XSTR + n0w + nt * 8 + qg];
                mma8(acc[0][nt], a[0], b0, b1);
                mma8(acc[1][nt], a[1], b0, b1);
            }
        }
        __syncthreads();
    }

    #pragma unroll
    for (int mt = 0; mt < 2; mt++) {
        int rr = r0 + mt * 16 + qg;
        int oa = o0 + rr;
        float bb0 = bias[oa], bb8 = bias[oa + 8];
        #pragma unroll
        for (int nt = 0; nt < 8; nt++) {
            int col = n0 + n0w + nt * 8 + 2 * p;
            size_t i0 = (size_t)oa * NTOK + col;
            size_t i8 = (size_t)(oa + 8) * NTOK + col;
            float2 v0 = make_float2(acc[mt][nt][0] + bb0, acc[mt][nt][1] + bb0);
            float2 v8 = make_float2(acc[mt][nt][2] + bb8, acc[mt][nt][3] + bb8);
            if (Yh) {
                *(uint32_t*)&Yh[i0] = pack2(v0.x, v0.y);
                *(uint32_t*)&Yh[i8] = pack2(v8.x, v8.y);
            } else {
                float2 r0v = *(const float2*)&Rb[i0];
                float2 r8v = *(const float2*)&Rb[i8];
                v0.x += r0v.x; v0.y += r0v.y;
                v8.x += r8v.x; v8.y += r8v.y;
                *(float2*)&Yb[i0] = v0;
                *(float2*)&Yb[i8] = v8;
            }
        }
    }
}

// Fused Q/K/V projection: grid.y in [0,6) = which*2 + o-tile(128). fp16 out.
__global__ void __launch_bounds__(256) qkv_mma_kernel()
{
    __shared__ float Ws[128 * WSTR];
    __shared__ float Xs[32 * XSTR];

    const int b     = blockIdx.z;
    const int which = blockIdx.y >> 1;
    const int o0    = (blockIdx.y & 1) * 128;
    const int n0    = blockIdx.x * 128;

    const float* W  = g_wr + (size_t)which * CCH * CCH;
    const float* Xb = g_xr + (size_t)b * CCH * NTOK;
    __half* Yh = g_qkvh + ((size_t)which * BATCH + b) * CCH * NTOK;

    proj_body(W, g_bias + which * CCH, Xb, nullptr, Yh, nullptr, o0, n0, Ws, Xs);
}

// Output projection (+residual): full precision output.
__global__ void __launch_bounds__(256) oproj_mma_kernel(
    float* __restrict__ out, const float* __restrict__ x)
{
    __shared__ float Ws[128 * WSTR];
    __shared__ float Xs[32 * XSTR];

    const int b  = blockIdx.z;
    const int o0 = blockIdx.y * 128;
    const int n0 = blockIdx.x * 128;

    const float* W  = g_wr + 3ull * CCH * CCH;
    const float* Xb = g_attn + (size_t)b * CCH * NTOK;
    const float* Rb = x + (size_t)b * CCH * NTOK;
    float* Yb = out + (size_t)b * CCH * NTOK;

    proj_body(W, g_bias + 3 * CCH, Xb, Yb, nullptr, Rb, o0, n0, Ws, Xs);
}

// ============================================================================
// Attention v7: fp16 m16n8k16 MMAs (2x tensor rate vs tf32, same mantissa).
// P fragments = direct f16x2 packs of S accumulators (no permutation/shuffle).
// K/V smem word layout KVW(row,w) = 4*row + (w&3) + (w>>2)*132:
// bank = (4*row + w) mod 32 -> B-frag loads & V staging conflict-free.
// ============================================================================
#define KVW(row, w) (4 * (row) + ((w) & 3) + ((w) >> 2) * 132)
#define KVWORDS 524

__global__ void __launch_bounds__(128, 4) attn_mma_kernel()
{
    __shared__ uint32_t Ku[2][KVWORDS];
    __shared__ uint32_t Vu[2][KVWORDS];

    const int t = threadIdx.x, w = t >> 5, lane = t & 31;
    const int qg = lane >> 2, p = lane & 3;
    const int b = blockIdx.z, h = blockIdx.y, q0 = blockIdx.x * 128;

    const size_t ho = ((size_t)b * CCH + h * HD) * NTOK;
    const uint16_t* Q16 = (const uint16_t*)(g_qkvh + ho);
    const uint32_t* KuG = (const uint32_t*)(g_qkvh + (size_t)BATCH * CCH * NTOK + ho);
    const uint32_t* VuG = (const uint32_t*)(g_qkvh + 2ull * BATCH * CCH * NTOK + ho);
    float* O = g_attn + ho;

    // ---- Q A-fragments (m16n8k16): d-pairs packed from [d][n] fp16 ----
    const int rbase = q0 + w * 32 + qg;
    uint32_t aq[2][2][4];
    #pragma unroll
    for (int mt = 0; mt < 2; mt++)
        #pragma unroll
        for (int s = 0; s < 2; s++) {
            int i = rbase + mt * 16;
            int d = 16 * s + 2 * p;
            aq[mt][s][0] = (uint32_t)Q16[d * NTOK + i]           | ((uint32_t)Q16[(d + 1) * NTOK + i] << 16);
            aq[mt][s][1] = (uint32_t)Q16[d * NTOK + i + 8]       | ((uint32_t)Q16[(d + 1) * NTOK + i + 8] << 16);
            aq[mt][s][2] = (uint32_t)Q16[(d + 8) * NTOK + i]     | ((uint32_t)Q16[(d + 9) * NTOK + i] << 16);
            aq[mt][s][3] = (uint32_t)Q16[(d + 8) * NTOK + i + 8] | ((uint32_t)Q16[(d + 9) * NTOK + i + 8] << 16);
        }

    float oc[2][4][4];
    #pragma unroll
    for (int mt = 0; mt < 2; mt++)
        #pragma unroll
        for (int nt = 0; nt < 4; nt++)
            #pragma unroll
            for (int k = 0; k < 4; k++) oc[mt][nt][k] = 0.f;
    float rs[2][2] = {{0.f, 0.f}, {0.f, 0.f}};

    // ---- staging assignments ----
    const int j2  = (t & 3) + 4 * (t >> 5);     // K: j-pair index 0..15
    const int w0b = (t >> 2) & 7;               // K: d-word base 0..7 (+8)
    const int dvv = (t & 7) + 8 * ((t >> 5) & 3); // V: row 0..31
    const int wvb = (t >> 3) & 3;               // V: word base (+4*it)

    // prefetch chunk 0
    uint32_t kp[2][2], vp[4];
    #pragma unroll
    for (int it = 0; it < 2; it++) {
        int w0 = w0b + 8 * it;
        kp[it][0] = KuG[1024 * w0 + j2];
        kp[it][1] = KuG[1024 * w0 + 512 + j2];
    }
    #pragma unroll
    for (int it = 0; it < 4; it++)
        vp[it] = VuG[dvv * 512 + wvb + 4 * it];

    for (int c = 0; c < 32; c++) {
        uint32_t* Kc = Ku[c & 1];
        uint32_t* Vc = Vu[c & 1];

        // ---- stage: K local 2x2 transpose (prmt), V direct ----
        #pragma unroll
        for (int it = 0; it < 2; it++) {
            int w0 = w0b + 8 * it;
            Kc[KVW(2 * j2, w0)]     = prmt(kp[it][0], kp[it][1], 0x5410);
            Kc[KVW(2 * j2 + 1, w0)] = prmt(kp[it][0], kp[it][1], 0x7632);
        }
        #pragma unroll
        for (int it = 0; it < 4; it++)
            Vc[KVW(dvv, wvb + 4 * it)] = vp[it];
        __syncthreads();

        // ---- prefetch next chunk ----
        if (c < 31) {
            const int ktw = (c + 1) * 16;
            #pragma unroll
            for (int it = 0; it < 2; it++) {
                int w0 = w0b + 8 * it;
                kp[it][0] = KuG[1024 * w0 + ktw + j2];
                kp[it][1] = KuG[1024 * w0 + 512 + ktw + j2];
            }
            #pragma unroll
            for (int it = 0; it < 4; it++)
                vp[it] = VuG[dvv * 512 + ktw + wvb + 4 * it];
        }

        // ---- MMA1: S(log2 domain) = Q K^T (16 fp16 k16 MMAs) ----
        float sc[2][4][4];
        #pragma unroll
        for (int mt = 0; mt < 2; mt++)
            #pragma unroll
            for (int nt = 0; nt < 4; nt++)
                #pragma unroll
                for (int k = 0; k < 4; k++) sc[mt][nt][k] = 0.f;

        #pragma unroll
        for (int s = 0; s < 2; s++)
            #pragma unroll
            for (int nt = 0; nt < 4; nt++) {
                uint32_t b0 = Kc[KVW(nt * 8 + qg, 8 * s + p)];
                uint32_t b1 = Kc[KVW(nt * 8 + qg, 8 * s + p + 4)];
                mma16(sc[0][nt], aq[0][s], b0, b1);
                mma16(sc[1][nt], aq[1][s], b0, b1);
            }

        // ---- exp2 via MUFU + rowsum partials ----
        #pragma unroll
        for (int mt = 0; mt < 2; mt++)
            #pragma unroll
            for (int nt = 0; nt < 4; nt++) {
                float e0 = fexp2(sc[mt][nt][0]);
                float e1 = fexp2(sc[mt][nt][1]);
                float e2 = fexp2(sc[mt][nt][2]);
                float e3 = fexp2(sc[mt][nt][3]);
                rs[mt][0] += e0 + e1;
                rs[mt][1] += e2 + e3;
                sc[mt][nt][0] = e0; sc[mt][nt][1] = e1;
                sc[mt][nt][2] = e2; sc[mt][nt][3] = e3;
            }

        // ---- MMA2: O += P V^T; P A-frags = direct f16x2 packs ----
        #pragma unroll
        for (int s = 0; s < 2; s++) {
            uint32_t ap[2][4];
            #pragma unroll
            for (int mt = 0; mt < 2; mt++) {
                ap[mt][0] = pack2(sc[mt][2 * s][0],     sc[mt][2 * s][1]);
                ap[mt][1] = pack2(sc[mt][2 * s][2],     sc[mt][2 * s][3]);
                ap[mt][2] = pack2(sc[mt][2 * s + 1][0], sc[mt][2 * s + 1][1]);
                ap[mt][3] = pack2(sc[mt][2 * s + 1][2], sc[mt][2 * s + 1][3]);
            }
            #pragma unroll
            for (int nt = 0; nt < 4; nt++) {
                uint32_t b0 = Vc[KVW(nt * 8 + qg, 8 * s + p)];
                uint32_t b1 = Vc[KVW(nt * 8 + qg, 8 * s + p + 4)];
                mma16(oc[0][nt], ap[0], b0, b1);
                mma16(oc[1][nt], ap[1], b0, b1);
            }
        }
    }

    // ---- normalize + store O tf32-rounded ----
    #pragma unroll
    for (int mt = 0; mt < 2; mt++) {
        float s0 = rs[mt][0], s1 = rs[mt][1];
        s0 += __shfl_xor_sync(0xffffffffu, s0, 1);
        s0 += __shfl_xor_sync(0xffffffffu, s0, 2);
        s1 += __shfl_xor_sync(0xffffffffu, s1, 1);
        s1 += __shfl_xor_sync(0xffffffffu, s1, 2);
        float r0i = 1.0f / s0, r1i = 1.0f / s1;
        int r = rbase + mt * 16;
        #pragma unroll
        for (int nt = 0; nt < 4; nt++) {
            float* Oa = O + (size_t)(nt * 8 + 2 * p) * NTOK;
            float* Ob = O + (size_t)(nt * 8 + 2 * p + 1) * NTOK;
            Oa[r]     = __uint_as_float(f2tf32(oc[mt][nt][0] * r0i));
            Ob[r]     = __uint_as_float(f2tf32(oc[mt][nt][1] * r0i));
            Oa[r + 8] = __uint_as_float(f2tf32(oc[mt][nt][2] * r1i));
            Ob[r + 8] = __uint_as_float(f2tf32(oc[mt][nt][3] * r1i));
        }
    }
}

// ============================================================================
extern "C" void kernel_launch(void* const* d_in, const int* in_sizes, int n_in,
                              void* d_out, int out_size)
{
    const float* x  = (const float*)d_in[0];
    const float* Wq = (const float*)d_in[1];
    const float* bq = (const float*)d_in[2];
    const float* Wk = (const float*)d_in[3];
    const float* bk = (const float*)d_in[4];
    const float* Wv = (const float*)d_in[5];
    const float* bv = (const float*)d_in[6];
    const float* Wo = (const float*)d_in[7];
    const float* bo = (const float*)d_in[8];
    float* out = (float*)d_out;

    bias_copy_kernel<<<(4 * CCH + 255) / 256, 256>>>(bq, bk, bv, bo);
    preround_kernel<<<(NX4 + 4 * NW4 + 255) / 256, 256>>>(x, Wq, Wk, Wv, Wo);

    qkv_mma_kernel<<<dim3(NTOK / 128, 6, BATCH), 256>>>();
    attn_mma_kernel<<<dim3(NTOK / 128, HEADS, BATCH), 128>>>();
    oproj_mma_kernel<<<dim3(NTOK / 128, CCH / 128, BATCH), 256>>>(out, x);
}

// round 15
// speedup vs baseline: 1.4438x; 1.1163x over previous
#include <cuda_runtime.h>
#include <cuda_fp16.h>
#include <cstdint>

#define BATCH 8
#define CCH   256
#define NTOK  1024
#define HEADS 8
#define HD    32

// -------- scratch --------
__device__ __half  g_qkvh[3ull * BATCH * CCH * NTOK];       // fp16 Q(scaled),K,V [w][b][c][n]
__device__ uint32_t g_oh[(size_t)BATCH * (CCH / 2) * NTOK]; // attn O, fp16 pairs [b][kp][n]
__device__ uint32_t g_xh[(size_t)BATCH * (CCH / 2) * NTOK]; // x, fp16 pairs [b][kp][n]
__device__ uint32_t g_wh[4ull * CCH * (CCH / 2)];           // W fp16 pairs [which][o][kp], Wq*QSC
__device__ float    g_bias[4 * CCH];                        // bq*QSC, bk, bv, bo

// log2(e)/sqrt(32): folded into Wq/bq so attention scores land in exp2 domain
#define QSC 0.2550348942479215f

__device__ __forceinline__ float fexp2(float z) {
    float r;
    asm("ex2.approx.f32 %0, %1;" : "=f"(r) : "f"(z));
    return r;
}
// pack two fp32 -> f16x2 {lo, hi}
__device__ __forceinline__ uint32_t pack2(float lo, float hi) {
    uint32_t d;
    asm("cvt.rn.f16x2.f32 %0, %1, %2;" : "=r"(d) : "f"(hi), "f"(lo));
    return d;
}
__device__ __forceinline__ uint32_t prmt(uint32_t a, uint32_t b, uint32_t sel) {
    uint32_t d;
    asm("prmt.b32 %0, %1, %2, %3;" : "=r"(d) : "r"(a), "r"(b), "r"(sel));
    return d;
}
__device__ __forceinline__ void mma16(float* d, const uint32_t* a, uint32_t b0, uint32_t b1) {
    asm volatile("mma.sync.aligned.m16n8k16.row.col.f32.f16.f16.f32 "
        "{%0,%1,%2,%3}, {%4,%5,%6,%7}, {%8,%9}, {%0,%1,%2,%3};"
        : "+f"(d[0]), "+f"(d[1]), "+f"(d[2]), "+f"(d[3])
        : "r"(a[0]), "r"(a[1]), "r"(a[2]), "r"(a[3]), "r"(b0), "r"(b1));
}

// ============================================================================
// Pre-round: pack x and 4 weights into fp16 k-pair words (Wq pre-scaled).
// x -> g_xh [b][kp][n]; W -> g_wh [which][o][kp].
// ============================================================================
#define NXU4 (BATCH * (CCH / 2) * NTOK / 4)   // 262144 uint4 for x
#define NWU4 (CCH * (CCH / 2) / 4)            // 8192 uint4 per weight

__global__ void __launch_bounds__(256) preround_kernel(
    const float* __restrict__ x,
    const float* __restrict__ Wq, const float* __restrict__ Wk,
    const float* __restrict__ Wv, const float* __restrict__ Wo)
{
    int i = blockIdx.x * 256 + threadIdx.x;
    if (i < NXU4) {
        int wi = i * 4;
        int b = wi >> 17;            // 128*1024 words per batch
        int rem = wi & 131071;
        int kp = rem >> 10, n = rem & 1023;
        const float* base = x + ((size_t)b * CCH + 2 * kp) * NTOK + n;
        float4 a = *(const float4*)base;
        float4 c = *(const float4*)(base + NTOK);
        uint4 o;
        o.x = pack2(a.x, c.x); o.y = pack2(a.y, c.y);
        o.z = pack2(a.z, c.z); o.w = pack2(a.w, c.w);
        *(uint4*)(g_xh + wi) = o;
    } else {
        int j = i - NXU4;
        int which = j >> 13;
        int k4 = j & (NWU4 - 1);
        int wi = k4 * 4;
        int o = wi >> 7;
        int kp = wi & 127;
        const float* W = (which == 0) ? Wq : (which == 1) ? Wk : (which == 2) ? Wv : Wo;
        float scale = (which == 0) ? QSC : 1.0f;
        const float* base = W + (size_t)o * CCH + 2 * kp;
        float4 a = *(const float4*)base;
        float4 c = *(const float4*)(base + 4);
        uint4 ov;
        ov.x = pack2(a.x * scale, a.y * scale);
        ov.y = pack2(a.z * scale, a.w * scale);
        ov.z = pack2(c.x * scale, c.y * scale);
        ov.w = pack2(c.z * scale, c.w * scale);
        *(uint4*)(g_wh + (size_t)which * 32768 + wi) = ov;
    }
}

__global__ void __launch_bounds__(256) bias_copy_kernel(
    const float* __restrict__ bq, const float* __restrict__ bk,
    const float* __restrict__ bv, const float* __restrict__ bo)
{
    int i = threadIdx.x + blockIdx.x * 256;
    if (i < CCH)          g_bias[i] = bq[i] * QSC;
    else if (i < 2 * CCH) g_bias[i] = bk[i - CCH];
    else if (i < 3 * CCH) g_bias[i] = bv[i - 2 * CCH];
    else if (i < 4 * CCH) g_bias[i] = bo[i - 3 * CCH];
}

// ============================================================================
// fp16 GEMM body: Y[o][n] = sum_c W[o][c]*X[c][n] + bias[o].
// W: [o][kp] words; X: [kp][n] words. Block 128x128, 8 warps 4x2,
// warp tile 32x64, BK=32 c (16 kp words, 2 k16 steps). uint4 staging.
// Yh != null -> fp16 [c][n] output (qkv); else fp32 + residual (oproj).
// ============================================================================
#define WS 20
#define XS 132

__device__ __forceinline__ void proj_body_h16(
    const uint32_t* __restrict__ Wg,   // [256 o][128 kp]
    const float* __restrict__ bias,
    const uint32_t* __restrict__ Xg,   // [128 kp][1024 n]
    __half* __restrict__ Yh, float* __restrict__ Yf,
    const float* __restrict__ Rb, int o0, int n0,
    uint32_t* Wsh, uint32_t* Xsh)
{
    const int t = threadIdx.x, lane = t & 31, w = t >> 5;
    const int qg = lane >> 2, p = lane & 3;
    const int r0  = (w >> 1) * 32;
    const int n0w = (w & 1) * 64;

    // staging: W rows 0..127, 2 threads/row each copying 2 uint4 (8 words)
    const int so = t >> 1, sh = (t & 1) * 8;
    // X: 16 kp rows x 128 n words; thread handles rows sk, sk+8, one uint4 each
    const int sk = t >> 5, sn4 = t & 31;

    float acc[2][8][4];
    #pragma unroll
    for (int mt = 0; mt < 2; mt++)
        #pragma unroll
        for (int nt = 0; nt < 8; nt++)
            #pragma unroll
            for (int k = 0; k < 4; k++) acc[mt][nt][k] = 0.f;

    uint4 wf[2], xf[2];
    wf[0] = *(const uint4*)&Wg[(o0 + so) * 128 + sh];
    wf[1] = *(const uint4*)&Wg[(o0 + so) * 128 + sh + 4];
    xf[0] = *(const uint4*)&Xg[(size_t)sk * NTOK + n0 + sn4 * 4];
    xf[1] = *(const uint4*)&Xg[(size_t)(sk + 8) * NTOK + n0 + sn4 * 4];

    for (int k0 = 0; k0 < CCH; k0 += 32) {
        *(uint4*)&Wsh[so * WS + sh]     = wf[0];
        *(uint4*)&Wsh[so * WS + sh + 4] = wf[1];
        *(uint4*)&Xsh[sk * XS + sn4 * 4]       = xf[0];
        *(uint4*)&Xsh[(sk + 8) * XS + sn4 * 4] = xf[1];
        __syncthreads();

        if (k0 + 32 < CCH) {
            const int kpn = (k0 + 32) >> 1;
            wf[0] = *(const uint4*)&Wg[(o0 + so) * 128 + kpn + sh];
            wf[1] = *(const uint4*)&Wg[(o0 + so) * 128 + kpn + sh + 4];
            xf[0] = *(const uint4*)&Xg[(size_t)(kpn + sk) * NTOK + n0 + sn4 * 4];
            xf[1] = *(const uint4*)&Xg[(size_t)(kpn + sk + 8) * NTOK + n0 + sn4 * 4];
        }

        #pragma unroll
        for (int s = 0; s < 2; s++) {
            uint32_t a[2][4];
            #pragma unroll
            for (int mt = 0; mt < 2; mt++) {
                int rr = r0 + mt * 16 + qg;
                a[mt][0] = Wsh[rr * WS + 8 * s + p];
                a[mt][1] = Wsh[(rr + 8) * WS + 8 * s + p];
                a[mt][2] = Wsh[rr * WS + 8 * s + p + 4];
                a[mt][3] = Wsh[(rr + 8) * WS + 8 * s + p + 4];
            }
            #pragma unroll
            for (int nt = 0; nt < 8; nt++) {
                uint32_t b0 = Xsh[(8 * s + p) * XS + n0w + nt * 8 + qg];
                uint32_t b1 = Xsh[(8 * s + p + 4) * XS + n0w + nt * 8 + qg];
                mma16(acc[0][nt], a[0], b0, b1);
                mma16(acc[1][nt], a[1], b0, b1);
            }
        }
        __syncthreads();
    }

    #pragma unroll
    for (int mt = 0; mt < 2; mt++) {
        int rr = r0 + mt * 16 + qg;
        int oa = o0 + rr;
        float bb0 = bias[oa], bb8 = bias[oa + 8];
        #pragma unroll
        for (int nt = 0; nt < 8; nt++) {
            int col = n0 + n0w + nt * 8 + 2 * p;
            size_t i0 = (size_t)oa * NTOK + col;
            size_t i8 = (size_t)(oa + 8) * NTOK + col;
            float2 v0 = make_float2(acc[mt][nt][0] + bb0, acc[mt][nt][1] + bb0);
            float2 v8 = make_float2(acc[mt][nt][2] + bb8, acc[mt][nt][3] + bb8);
            if (Yh) {
                *(uint32_t*)&Yh[i0] = pack2(v0.x, v0.y);
                *(uint32_t*)&Yh[i8] = pack2(v8.x, v8.y);
            } else {
                float2 r0v = *(const float2*)&Rb[i0];
                float2 r8v = *(const float2*)&Rb[i8];
                v0.x += r0v.x; v0.y += r0v.y;
                v8.x += r8v.x; v8.y += r8v.y;
                *(float2*)&Yf[i0] = v0;
                *(float2*)&Yf[i8] = v8;
            }
        }
    }
}

// Fused Q/K/V projection: grid.y in [0,6) = which*2 + o-tile(128). fp16 out.
__global__ void __launch_bounds__(256) qkv_mma_kernel()
{
    __shared__ uint32_t Wsh[128 * WS];
    __shared__ uint32_t Xsh[16 * XS];

    const int b     = blockIdx.z;
    const int which = blockIdx.y >> 1;
    const int o0    = (blockIdx.y & 1) * 128;
    const int n0    = blockIdx.x * 128;

    const uint32_t* Wg = g_wh + (size_t)which * 32768;
    const uint32_t* Xg = g_xh + (size_t)b * 128 * NTOK;
    __half* Yh = g_qkvh + ((size_t)which * BATCH + b) * CCH * NTOK;

    proj_body_h16(Wg, g_bias + which * CCH, Xg, Yh, nullptr, nullptr, o0, n0, Wsh, Xsh);
}

// Output projection (+residual): reads packed attn O, fp32 out.
__global__ void __launch_bounds__(256) oproj_mma_kernel(
    float* __restrict__ out, const float* __restrict__ x)
{
    __shared__ uint32_t Wsh[128 * WS];
    __shared__ uint32_t Xsh[16 * XS];

    const int b  = blockIdx.z;
    const int o0 = blockIdx.y * 128;
    const int n0 = blockIdx.x * 128;

    const uint32_t* Wg = g_wh + 3ull * 32768;
    const uint32_t* Xg = g_oh + (size_t)b * 128 * NTOK;
    const float* Rb = x + (size_t)b * CCH * NTOK;
    float* Yf = out + (size_t)b * CCH * NTOK;

    proj_body_h16(Wg, g_bias + 3 * CCH, Xg, nullptr, Yf, Rb, o0, n0, Wsh, Xsh);
}

// ============================================================================
// Attention (compute identical to Round 12): fp16 m16n8k16, MUFU exp2,
// direct f16x2 P packs. Epilogue writes packed fp16 O pairs to g_oh [kp][n].
// ============================================================================
#define KVW(row, w) (4 * (row) + ((w) & 3) + ((w) >> 2) * 132)
#define KVWORDS 524

__global__ void __launch_bounds__(128, 4) attn_mma_kernel()
{
    __shared__ uint32_t Ku[2][KVWORDS];
    __shared__ uint32_t Vu[2][KVWORDS];

    const int t = threadIdx.x, w = t >> 5, lane = t & 31;
    const int qg = lane >> 2, p = lane & 3;
    const int b = blockIdx.z, h = blockIdx.y, q0 = blockIdx.x * 128;

    const size_t ho = ((size_t)b * CCH + h * HD) * NTOK;
    const uint16_t* Q16 = (const uint16_t*)(g_qkvh + ho);
    const uint32_t* KuG = (const uint32_t*)(g_qkvh + (size_t)BATCH * CCH * NTOK + ho);
    const uint32_t* VuG = (const uint32_t*)(g_qkvh + 2ull * BATCH * CCH * NTOK + ho);
    uint32_t* Oh = g_oh + ((size_t)b * 128 + h * 16) * NTOK;

    const int rbase = q0 + w * 32 + qg;
    uint32_t aq[2][2][4];
    #pragma unroll
    for (int mt = 0; mt < 2; mt++)
        #pragma unroll
        for (int s = 0; s < 2; s++) {
            int i = rbase + mt * 16;
            int d = 16 * s + 2 * p;
            aq[mt][s][0] = (uint32_t)Q16[d * NTOK + i]           | ((uint32_t)Q16[(d + 1) * NTOK + i] << 16);
            aq[mt][s][1] = (uint32_t)Q16[d * NTOK + i + 8]       | ((uint32_t)Q16[(d + 1) * NTOK + i + 8] << 16);
            aq[mt][s][2] = (uint32_t)Q16[(d + 8) * NTOK + i]     | ((uint32_t)Q16[(d + 9) * NTOK + i] << 16);
            aq[mt][s][3] = (uint32_t)Q16[(d + 8) * NTOK + i + 8] | ((uint32_t)Q16[(d + 9) * NTOK + i + 8] << 16);
        }

    float oc[2][4][4];
    #pragma unroll
    for (int mt = 0; mt < 2; mt++)
        #pragma unroll
        for (int nt = 0; nt < 4; nt++)
            #pragma unroll
            for (int k = 0; k < 4; k++) oc[mt][nt][k] = 0.f;
    float rs[2][2] = {{0.f, 0.f}, {0.f, 0.f}};

    const int j2  = (t & 3) + 4 * (t >> 5);
    const int w0b = (t >> 2) & 7;
    const int dvv = (t & 7) + 8 * ((t >> 5) & 3);
    const int wvb = (t >> 3) & 3;

    uint32_t kp[2][2], vp[4];
    #pragma unroll
    for (int it = 0; it < 2; it++) {
        int w0 = w0b + 8 * it;
        kp[it][0] = KuG[1024 * w0 + j2];
        kp[it][1] = KuG[1024 * w0 + 512 + j2];
    }
    #pragma unroll
    for (int it = 0; it < 4; it++)
        vp[it] = VuG[dvv * 512 + wvb + 4 * it];

    for (int c = 0; c < 32; c++) {
        uint32_t* Kc = Ku[c & 1];
        uint32_t* Vc = Vu[c & 1];

        #pragma unroll
        for (int it = 0; it < 2; it++) {
            int w0 = w0b + 8 * it;
            Kc[KVW(2 * j2, w0)]     = prmt(kp[it][0], kp[it][1], 0x5410);
            Kc[KVW(2 * j2 + 1, w0)] = prmt(kp[it][0], kp[it][1], 0x7632);
        }
        #pragma unroll
        for (int it = 0; it < 4; it++)
            Vc[KVW(dvv, wvb + 4 * it)] = vp[it];
        __syncthreads();

        if (c < 31) {
            const int ktw = (c + 1) * 16;
            #pragma unroll
            for (int it = 0; it < 2; it++) {
                int w0 = w0b + 8 * it;
                kp[it][0] = KuG[1024 * w0 + ktw + j2];
                kp[it][1] = KuG[1024 * w0 + 512 + ktw + j2];
            }
            #pragma unroll
            for (int it = 0; it < 4; it++)
                vp[it] = VuG[dvv * 512 + ktw + wvb + 4 * it];
        }

        float sc[2][4][4];
        #pragma unroll
        for (int mt = 0; mt < 2; mt++)
            #pragma unroll
            for (int nt = 0; nt < 4; nt++)
                #pragma unroll
                for (int k = 0; k < 4; k++) sc[mt][nt][k] = 0.f;

        #pragma unroll
        for (int s = 0; s < 2; s++)
            #pragma unroll
            for (int nt = 0; nt < 4; nt++) {
                uint32_t b0 = Kc[KVW(nt * 8 + qg, 8 * s + p)];
                uint32_t b1 = Kc[KVW(nt * 8 + qg, 8 * s + p + 4)];
                mma16(sc[0][nt], aq[0][s], b0, b1);
                mma16(sc[1][nt], aq[1][s], b0, b1);
            }

        #pragma unroll
        for (int mt = 0; mt < 2; mt++)
            #pragma unroll
            for (int nt = 0; nt < 4; nt++) {
                float e0 = fexp2(sc[mt][nt][0]);
                float e1 = fexp2(sc[mt][nt][1]);
                float e2 = fexp2(sc[mt][nt][2]);
                float e3 = fexp2(sc[mt][nt][3]);
                rs[mt][0] += e0 + e1;
                rs[mt][1] += e2 + e3;
                sc[mt][nt][0] = e0; sc[mt][nt][1] = e1;
                sc[mt][nt][2] = e2; sc[mt][nt][3] = e3;
            }

        #pragma unroll
        for (int s = 0; s < 2; s++) {
            uint32_t ap[2][4];
            #pragma unroll
            for (int mt = 0; mt < 2; mt++) {
                ap[mt][0] = pack2(sc[mt][2 * s][0],     sc[mt][2 * s][1]);
                ap[mt][1] = pack2(sc[mt][2 * s][2],     sc[mt][2 * s][3]);
                ap[mt][2] = pack2(sc[mt][2 * s + 1][0], sc[mt][2 * s + 1][1]);
                ap[mt][3] = pack2(sc[mt][2 * s + 1][2], sc[mt][2 * s + 1][3]);
            }
            #pragma unroll
            for (int nt = 0; nt < 4; nt++) {
                uint32_t b0 = Vc[KVW(nt * 8 + qg, 8 * s + p)];
                uint32_t b1 = Vc[KVW(nt * 8 + qg, 8 * s + p + 4)];
                mma16(oc[0][nt], ap[0], b0, b1);
                mma16(oc[1][nt], ap[1], b0, b1);
            }
        }
    }

    // ---- normalize + store O as packed fp16 pairs [kp][n] ----
    #pragma unroll
    for (int mt = 0; mt < 2; mt++) {
        float s0 = rs[mt][0], s1 = rs[mt][1];
        s0 += __shfl_xor_sync(0xffffffffu, s0, 1);
        s0 += __shfl_xor_sync(0xffffffffu, s0, 2);
        s1 += __shfl_xor_sync(0xffffffffu, s1, 1);
        s1 += __shfl_xor_sync(0xffffffffu, s1, 2);
        float r0i = 1.0f / s0, r1i = 1.0f / s1;
        int r = rbase + mt * 16;
        #pragma unroll
        for (int nt = 0; nt < 4; nt++) {
            uint32_t* row = Oh + (size_t)(nt * 4 + p) * NTOK;
            row[r]     = pack2(oc[mt][nt][0] * r0i, oc[mt][nt][1] * r0i);
            row[r + 8] = pack2(oc[mt][nt][2] * r1i, oc[mt][nt][3] * r1i);
        }
    }
}

// ============================================================================
extern "C" void kernel_launch(void* const* d_in, const int* in_sizes, int n_in,
                              void* d_out, int out_size)
{
    const float* x  = (const float*)d_in[0];
    const float* Wq = (const float*)d_in[1];
    const float* bq = (const float*)d_in[2];
    const float* Wk = (const float*)d_in[3];
    const float* bk = (const float*)d_in[4];
    const float* Wv = (const float*)d_in[5];
    const float* bv = (const float*)d_in[6];
    const float* Wo = (const float*)d_in[7];
    const float* bo = (const float*)d_in[8];
    float* out = (float*)d_out;

    bias_copy_kernel<<<(4 * CCH + 255) / 256, 256>>>(bq, bk, bv, bo);
    preround_kernel<<<(NXU4 + 4 * NWU4 + 255) / 256, 256>>>(x, Wq, Wk, Wv, Wo);

    qkv_mma_kernel<<<dim3(NTOK / 128, 6, BATCH), 256>>>();
    attn_mma_kernel<<<dim3(NTOK / 128, HEADS, BATCH), 128>>>();
    oproj_mma_kernel<<<dim3(NTOK / 128, CCH / 128, BATCH), 256>>>(out, x);
}

// round 16
// speedup vs baseline: 1.5080x; 1.0444x over previous
#include <cuda_runtime.h>
#include <cuda_fp16.h>
#include <cstdint>

#define BATCH 8
#define CCH   256
#define NTOK  1024
#define HEADS 8
#define HD    32

// -------- scratch --------
__device__ __half  g_qkvh[3ull * BATCH * CCH * NTOK];       // fp16 Q(scaled),K,V [w][b][c][n]
__device__ uint32_t g_oh[(size_t)BATCH * (CCH / 2) * NTOK]; // attn O, fp16 pairs [b][kp][n]
__device__ uint32_t g_xh[(size_t)BATCH * (CCH / 2) * NTOK]; // x, fp16 pairs [b][kp][n]
__device__ uint32_t g_wh[4ull * CCH * (CCH / 2)];           // W fp16 pairs [which][o][kp], Wq*QSC
__device__ float    g_bias[4 * CCH];                        // bq*QSC, bk, bv, bo

// log2(e)/sqrt(32): folded into Wq/bq so attention scores land in exp2 domain
#define QSC 0.2550348942479215f

__device__ __forceinline__ float fexp2(float z) {
    float r;
    asm("ex2.approx.f32 %0, %1;" : "=f"(r) : "f"(z));
    return r;
}
// pack two fp32 -> f16x2 {lo, hi}
__device__ __forceinline__ uint32_t pack2(float lo, float hi) {
    uint32_t d;
    asm("cvt.rn.f16x2.f32 %0, %1, %2;" : "=r"(d) : "f"(hi), "f"(lo));
    return d;
}
__device__ __forceinline__ uint32_t prmt(uint32_t a, uint32_t b, uint32_t sel) {
    uint32_t d;
    asm("prmt.b32 %0, %1, %2, %3;" : "=r"(d) : "r"(a), "r"(b), "r"(sel));
    return d;
}
__device__ __forceinline__ void mma16(float* d, const uint32_t* a, uint32_t b0, uint32_t b1) {
    asm volatile("mma.sync.aligned.m16n8k16.row.col.f32.f16.f16.f32 "
        "{%0,%1,%2,%3}, {%4,%5,%6,%7}, {%8,%9}, {%0,%1,%2,%3};"
        : "+f"(d[0]), "+f"(d[1]), "+f"(d[2]), "+f"(d[3])
        : "r"(a[0]), "r"(a[1]), "r"(a[2]), "r"(a[3]), "r"(b0), "r"(b1));
}

// ============================================================================
// Pre-round: pack x + 4 weights into fp16 k-pair words; also stage biases.
// ============================================================================
#define NXU4 (BATCH * (CCH / 2) * NTOK / 4)   // 262144
#define NWU4 (CCH * (CCH / 2) / 4)            // 8192
#define NB   (4 * CCH)                        // 1024 bias values

__global__ void __launch_bounds__(256) preround_kernel(
    const float* __restrict__ x,
    const float* __restrict__ Wq, const float* __restrict__ Wk,
    const float* __restrict__ Wv, const float* __restrict__ Wo,
    const float* __restrict__ bq, const float* __restrict__ bk,
    const float* __restrict__ bv, const float* __restrict__ bo)
{
    int i = blockIdx.x * 256 + threadIdx.x;
    if (i < NXU4) {
        int wi = i * 4;
        int b = wi >> 17;
        int rem = wi & 131071;
        int kp = rem >> 10, n = rem & 1023;
        const float* base = x + ((size_t)b * CCH + 2 * kp) * NTOK + n;
        float4 a = *(const float4*)base;
        float4 c = *(const float4*)(base + NTOK);
        uint4 o;
        o.x = pack2(a.x, c.x); o.y = pack2(a.y, c.y);
        o.z = pack2(a.z, c.z); o.w = pack2(a.w, c.w);
        *(uint4*)(g_xh + wi) = o;
    } else if (i < NXU4 + 4 * NWU4) {
        int j = i - NXU4;
        int which = j >> 13;
        int k4 = j & (NWU4 - 1);
        int wi = k4 * 4;
        int o = wi >> 7;
        int kp = wi & 127;
        const float* W = (which == 0) ? Wq : (which == 1) ? Wk : (which == 2) ? Wv : Wo;
        float scale = (which == 0) ? QSC : 1.0f;
        const float* base = W + (size_t)o * CCH + 2 * kp;
        float4 a = *(const float4*)base;
        float4 c = *(const float4*)(base + 4);
        uint4 ov;
        ov.x = pack2(a.x * scale, a.y * scale);
        ov.y = pack2(a.z * scale, a.w * scale);
        ov.z = pack2(c.x * scale, c.y * scale);
        ov.w = pack2(c.z * scale, c.w * scale);
        *(uint4*)(g_wh + (size_t)which * 32768 + wi) = ov;
    } else {
        int j = i - NXU4 - 4 * NWU4;
        if (j < NB) {
            if (j < CCH)          g_bias[j] = bq[j] * QSC;
            else if (j < 2 * CCH) g_bias[j] = bk[j - CCH];
            else if (j < 3 * CCH) g_bias[j] = bv[j - 2 * CCH];
            else                  g_bias[j] = bo[j - 3 * CCH];
        }
    }
}

// ============================================================================
// fp16 GEMM body (unchanged from Round 15).
// ============================================================================
#define WS 20
#define XS 132

__device__ __forceinline__ void proj_body_h16(
    const uint32_t* __restrict__ Wg, const float* __restrict__ bias,
    const uint32_t* __restrict__ Xg,
    __half* __restrict__ Yh, float* __restrict__ Yf,
    const float* __restrict__ Rb, int o0, int n0,
    uint32_t* Wsh, uint32_t* Xsh)
{
    const int t = threadIdx.x, lane = t & 31, w = t >> 5;
    const int qg = lane >> 2, p = lane & 3;
    const int r0  = (w >> 1) * 32;
    const int n0w = (w & 1) * 64;

    const int so = t >> 1, sh = (t & 1) * 8;
    const int sk = t >> 5, sn4 = t & 31;

    float acc[2][8][4];
    #pragma unroll
    for (int mt = 0; mt < 2; mt++)
        #pragma unroll
        for (int nt = 0; nt < 8; nt++)
            #pragma unroll
            for (int k = 0; k < 4; k++) acc[mt][nt][k] = 0.f;

    uint4 wf[2], xf[2];
    wf[0] = *(const uint4*)&Wg[(o0 + so) * 128 + sh];
    wf[1] = *(const uint4*)&Wg[(o0 + so) * 128 + sh + 4];
    xf[0] = *(const uint4*)&Xg[(size_t)sk * NTOK + n0 + sn4 * 4];
    xf[1] = *(const uint4*)&Xg[(size_t)(sk + 8) * NTOK + n0 + sn4 * 4];

    for (int k0 = 0; k0 < CCH; k0 += 32) {
        *(uint4*)&Wsh[so * WS + sh]     = wf[0];
        *(uint4*)&Wsh[so * WS + sh + 4] = wf[1];
        *(uint4*)&Xsh[sk * XS + sn4 * 4]       = xf[0];
        *(uint4*)&Xsh[(sk + 8) * XS + sn4 * 4] = xf[1];
        __syncthreads();

        if (k0 + 32 < CCH) {
            const int kpn = (k0 + 32) >> 1;
            wf[0] = *(const uint4*)&Wg[(o0 + so) * 128 + kpn + sh];
            wf[1] = *(const uint4*)&Wg[(o0 + so) * 128 + kpn + sh + 4];
            xf[0] = *(const uint4*)&Xg[(size_t)(kpn + sk) * NTOK + n0 + sn4 * 4];
            xf[1] = *(const uint4*)&Xg[(size_t)(kpn + sk + 8) * NTOK + n0 + sn4 * 4];
        }

        #pragma unroll
        for (int s = 0; s < 2; s++) {
            uint32_t a[2][4];
            #pragma unroll
            for (int mt = 0; mt < 2; mt++) {
                int rr = r0 + mt * 16 + qg;
                a[mt][0] = Wsh[rr * WS + 8 * s + p];
                a[mt][1] = Wsh[(rr + 8) * WS + 8 * s + p];
                a[mt][2] = Wsh[rr * WS + 8 * s + p + 4];
                a[mt][3] = Wsh[(rr + 8) * WS + 8 * s + p + 4];
            }
            #pragma unroll
            for (int nt = 0; nt < 8; nt++) {
                uint32_t b0 = Xsh[(8 * s + p) * XS + n0w + nt * 8 + qg];
                uint32_t b1 = Xsh[(8 * s + p + 4) * XS + n0w + nt * 8 + qg];
                mma16(acc[0][nt], a[0], b0, b1);
                mma16(acc[1][nt], a[1], b0, b1);
            }
        }
        __syncthreads();
    }

    #pragma unroll
    for (int mt = 0; mt < 2; mt++) {
        int rr = r0 + mt * 16 + qg;
        int oa = o0 + rr;
        float bb0 = bias[oa], bb8 = bias[oa + 8];
        #pragma unroll
        for (int nt = 0; nt < 8; nt++) {
            int col = n0 + n0w + nt * 8 + 2 * p;
            size_t i0 = (size_t)oa * NTOK + col;
            size_t i8 = (size_t)(oa + 8) * NTOK + col;
            float2 v0 = make_float2(acc[mt][nt][0] + bb0, acc[mt][nt][1] + bb0);
            float2 v8 = make_float2(acc[mt][nt][2] + bb8, acc[mt][nt][3] + bb8);
            if (Yh) {
                *(uint32_t*)&Yh[i0] = pack2(v0.x, v0.y);
                *(uint32_t*)&Yh[i8] = pack2(v8.x, v8.y);
            } else {
                float2 r0v = *(const float2*)&Rb[i0];
                float2 r8v = *(const float2*)&Rb[i8];
                v0.x += r0v.x; v0.y += r0v.y;
                v8.x += r8v.x; v8.y += r8v.y;
                *(float2*)&Yf[i0] = v0;
                *(float2*)&Yf[i8] = v8;
            }
        }
    }
}

__global__ void __launch_bounds__(256) qkv_mma_kernel()
{
    __shared__ uint32_t Wsh[128 * WS];
    __shared__ uint32_t Xsh[16 * XS];

    const int b     = blockIdx.z;
    const int which = blockIdx.y >> 1;
    const int o0    = (blockIdx.y & 1) * 128;
    const int n0    = blockIdx.x * 128;

    const uint32_t* Wg = g_wh + (size_t)which * 32768;
    const uint32_t* Xg = g_xh + (size_t)b * 128 * NTOK;
    __half* Yh = g_qkvh + ((size_t)which * BATCH + b) * CCH * NTOK;

    proj_body_h16(Wg, g_bias + which * CCH, Xg, Yh, nullptr, nullptr, o0, n0, Wsh, Xsh);
}

__global__ void __launch_bounds__(256) oproj_mma_kernel(
    float* __restrict__ out, const float* __restrict__ x)
{
    __shared__ uint32_t Wsh[128 * WS];
    __shared__ uint32_t Xsh[16 * XS];

    const int b  = blockIdx.z;
    const int o0 = blockIdx.y * 128;
    const int n0 = blockIdx.x * 128;

    const uint32_t* Wg = g_wh + 3ull * 32768;
    const uint32_t* Xg = g_oh + (size_t)b * 128 * NTOK;
    const float* Rb = x + (size_t)b * CCH * NTOK;
    float* Yf = out + (size_t)b * CCH * NTOK;

    proj_body_h16(Wg, g_bias + 3 * CCH, Xg, nullptr, Yf, Rb, o0, n0, Wsh, Xsh);
}

// ============================================================================
// Attention v8: 64-key staging per barrier (16 barriers instead of 32),
// rowsum via ones-column tensor MMA (deletes 32 FADD/chunk), fp16 m16n8k16,
// MUFU exp2. Word layout stride 260 === 132 === 4 (mod 32) keeps every
// staging store and B-frag load conflict-free (same proofs as v7).
// ============================================================================
#define KWRD(row, w) (4 * (row) + ((w) & 3) + ((w) >> 2) * 260)
#define KWORDS 1036   // 64 rows x 16 words
#define VWORDS 1948   // 32 rows x 32 words

__global__ void __launch_bounds__(128, 4) attn_mma_kernel()
{
    __shared__ uint32_t Ku[2][KWORDS];
    __shared__ uint32_t Vu[2][VWORDS];

    const int t = threadIdx.x, w = t >> 5, lane = t & 31;
    const int qg = lane >> 2, p = lane & 3;
    const int b = blockIdx.z, h = blockIdx.y, q0 = blockIdx.x * 128;

    const size_t ho = ((size_t)b * CCH + h * HD) * NTOK;
    const uint16_t* Q16 = (const uint16_t*)(g_qkvh + ho);
    const uint32_t* KuG = (const uint32_t*)(g_qkvh + (size_t)BATCH * CCH * NTOK + ho);
    const uint32_t* VuG = (const uint32_t*)(g_qkvh + 2ull * BATCH * CCH * NTOK + ho);
    uint32_t* Oh = g_oh + ((size_t)b * 128 + h * 16) * NTOK;

    // ---- Q A-fragments ----
    const int rbase = q0 + w * 32 + qg;
    uint32_t aq[2][2][4];
    #pragma unroll
    for (int mt = 0; mt < 2; mt++)
        #pragma unroll
        for (int s = 0; s < 2; s++) {
            int i = rbase + mt * 16;
            int d = 16 * s + 2 * p;
            aq[mt][s][0] = (uint32_t)Q16[d * NTOK + i]           | ((uint32_t)Q16[(d + 1) * NTOK + i] << 16);
            aq[mt][s][1] = (uint32_t)Q16[d * NTOK + i + 8]       | ((uint32_t)Q16[(d + 1) * NTOK + i + 8] << 16);
            aq[mt][s][2] = (uint32_t)Q16[(d + 8) * NTOK + i]     | ((uint32_t)Q16[(d + 9) * NTOK + i] << 16);
            aq[mt][s][3] = (uint32_t)Q16[(d + 8) * NTOK + i + 8] | ((uint32_t)Q16[(d + 9) * NTOK + i + 8] << 16);
        }

    float oc[2][4][4];
    #pragma unroll
    for (int mt = 0; mt < 2; mt++)
        #pragma unroll
        for (int nt = 0; nt < 4; nt++)
            #pragma unroll
            for (int k = 0; k < 4; k++) oc[mt][nt][k] = 0.f;
    float accS[2][4] = {{0.f, 0.f, 0.f, 0.f}, {0.f, 0.f, 0.f, 0.f}};

    // ones-column B fragment: col 0 of the synthetic tile = 1.0 for all keys
    const uint32_t oneb = (qg == 0) ? 0x3C003C00u : 0u;

    // ---- staging assignments (64 keys per chunk) ----
    const int j2  = (t & 3) + 4 * (t >> 5);       // key-pair within 32-half
    const int w0b = (t >> 2) & 7;                 // K d-word base (+8*it)
    const int dvv = (t & 7) + 8 * ((t >> 5) & 3); // V d row
    const int wvb = (t >> 3) & 3;                 // V word base (+4*it)

    uint32_t kp[2][2][2], vp[2][4];
    #pragma unroll
    for (int hh = 0; hh < 2; hh++) {
        #pragma unroll
        for (int it = 0; it < 2; it++) {
            int w0 = w0b + 8 * it;
            kp[hh][it][0] = KuG[1024 * w0 + 16 * hh + j2];
            kp[hh][it][1] = KuG[1024 * w0 + 512 + 16 * hh + j2];
        }
        #pragma unroll
        for (int it = 0; it < 4; it++)
            vp[hh][it] = VuG[dvv * 512 + 16 * hh + wvb + 4 * it];
    }

    for (int c = 0; c < 16; c++) {
        uint32_t* Kc = Ku[c & 1];
        uint32_t* Vc = Vu[c & 1];

        // ---- stage 64-key chunk ----
        #pragma unroll
        for (int hh = 0; hh < 2; hh++) {
            #pragma unroll
            for (int it = 0; it < 2; it++) {
                int w0 = w0b + 8 * it;
                int row = 2 * j2 + 32 * hh;
                Kc[KWRD(row, w0)]     = prmt(kp[hh][it][0], kp[hh][it][1], 0x5410);
                Kc[KWRD(row + 1, w0)] = prmt(kp[hh][it][0], kp[hh][it][1], 0x7632);
            }
            #pragma unroll
            for (int it = 0; it < 4; it++)
                Vc[KWRD(dvv, wvb + 4 * it + 16 * hh)] = vp[hh][it];
        }
        __syncthreads();

        // ---- prefetch next chunk ----
        if (c < 15) {
            const int ktw = (c + 1) * 32;
            #pragma unroll
            for (int hh = 0; hh < 2; hh++) {
                #pragma unroll
                for (int it = 0; it < 2; it++) {
                    int w0 = w0b + 8 * it;
                    kp[hh][it][0] = KuG[1024 * w0 + ktw + 16 * hh + j2];
                    kp[hh][it][1] = KuG[1024 * w0 + 512 + ktw + 16 * hh + j2];
                }
                #pragma unroll
                for (int it = 0; it < 4; it++)
                    vp[hh][it] = VuG[dvv * 512 + ktw + 16 * hh + wvb + 4 * it];
            }
        }

        // ---- two 32-key compute halves, no barrier between ----
        #pragma unroll
        for (int hh = 0; hh < 2; hh++) {
            float sc[2][4][4];
            #pragma unroll
            for (int mt = 0; mt < 2; mt++)
                #pragma unroll
                for (int nt = 0; nt < 4; nt++)
                    #pragma unroll
                    for (int k = 0; k < 4; k++) sc[mt][nt][k] = 0.f;

            #pragma unroll
            for (int s = 0; s < 2; s++)
                #pragma unroll
                for (int nt = 0; nt < 4; nt++) {
                    int row = 32 * hh + nt * 8 + qg;
                    uint32_t b0 = Kc[KWRD(row, 8 * s + p)];
                    uint32_t b1 = Kc[KWRD(row, 8 * s + p + 4)];
                    mma16(sc[0][nt], aq[0][s], b0, b1);
                    mma16(sc[1][nt], aq[1][s], b0, b1);
                }

            #pragma unroll
            for (int mt = 0; mt < 2; mt++)
                #pragma unroll
                for (int nt = 0; nt < 4; nt++) {
                    sc[mt][nt][0] = fexp2(sc[mt][nt][0]);
                    sc[mt][nt][1] = fexp2(sc[mt][nt][1]);
                    sc[mt][nt][2] = fexp2(sc[mt][nt][2]);
                    sc[mt][nt][3] = fexp2(sc[mt][nt][3]);
                }

            #pragma unroll
            for (int s = 0; s < 2; s++) {
                uint32_t ap[2][4];
                #pragma unroll
                for (int mt = 0; mt < 2; mt++) {
                    ap[mt][0] = pack2(sc[mt][2 * s][0],     sc[mt][2 * s][1]);
                    ap[mt][1] = pack2(sc[mt][2 * s][2],     sc[mt][2 * s][3]);
                    ap[mt][2] = pack2(sc[mt][2 * s + 1][0], sc[mt][2 * s + 1][1]);
                    ap[mt][3] = pack2(sc[mt][2 * s + 1][2], sc[mt][2 * s + 1][3]);
                }
                // rowsum via ones-column MMA (replaces FADD chain)
                mma16(accS[0], ap[0], oneb, oneb);
                mma16(accS[1], ap[1], oneb, oneb);
                #pragma unroll
                for (int nt = 0; nt < 4; nt++) {
                    int vw = 16 * hh + 8 * s + p;
                    uint32_t b0 = Vc[KWRD(nt * 8 + qg, vw)];
                    uint32_t b1 = Vc[KWRD(nt * 8 + qg, vw + 4)];
                    mma16(oc[0][nt], ap[0], b0, b1);
                    mma16(oc[1][nt], ap[1], b0, b1);
                }
            }
        }
    }

    // ---- normalize + store O as packed fp16 pairs [kp][n] ----
    #pragma unroll
    for (int mt = 0; mt < 2; mt++) {
        // rowsums live in p==0 lanes (col 0 of the ones tile); broadcast
        float s0 = __shfl_sync(0xffffffffu, accS[mt][0], lane & ~3);
        float s1 = __shfl_sync(0xffffffffu, accS[mt][2], lane & ~3);
        float r0i = 1.0f / s0, r1i = 1.0f / s1;
        int r = rbase + mt * 16;
        #pragma unroll
        for (int nt = 0; nt < 4; nt++) {
            uint32_t* row = Oh + (size_t)(nt * 4 + p) * NTOK;
            row[r]     = pack2(oc[mt][nt][0] * r0i, oc[mt][nt][1] * r0i);
            row[r + 8] = pack2(oc[mt][nt][2] * r1i, oc[mt][nt][3] * r1i);
        }
    }
}

// ============================================================================
extern "C" void kernel_launch(void* const* d_in, const int* in_sizes, int n_in,
                              void* d_out, int out_size)
{
    const float* x  = (const float*)d_in[0];
    const float* Wq = (const float*)d_in[1];
    const float* bq = (const float*)d_in[2];
    const float* Wk = (const float*)d_in[3];
    const float* bk = (const float*)d_in[4];
    const float* Wv = (const float*)d_in[5];
    const float* bv = (const float*)d_in[6];
    const float* Wo = (const float*)d_in[7];
    const float* bo = (const float*)d_in[8];
    float* out = (float*)d_out;

    preround_kernel<<<(NXU4 + 4 * NWU4 + NB + 255) / 256, 256>>>(
        x, Wq, Wk, Wv, Wo, bq, bk, bv, bo);

    qkv_mma_kernel<<<dim3(NTOK / 128, 6, BATCH), 256>>>();
    attn_mma_kernel<<<dim3(NTOK / 128, HEADS, BATCH), 128>>>();
    oproj_mma_kernel<<<dim3(NTOK / 128, CCH / 128, BATCH), 256>>>(out, x);
}

// round 17
// speedup vs baseline: 1.5137x; 1.0038x over previous
#include <cuda_runtime.h>
#include <cuda_fp16.h>
#include <cstdint>

#define BATCH 8
#define CCH   256
#define NTOK  1024
#define HEADS 8
#define HD    32

// -------- scratch --------
__device__ __half  g_qkvh[3ull * BATCH * CCH * NTOK];       // fp16 Q(scaled),K,V [w][b][c][n]
__device__ uint32_t g_oh[(size_t)BATCH * (CCH / 2) * NTOK]; // attn O, fp16 pairs [b][kp][n]
__device__ uint32_t g_xh[(size_t)BATCH * (CCH / 2) * NTOK]; // x, fp16 pairs [b][kp][n]
__device__ uint32_t g_wh[4ull * CCH * (CCH / 2)];           // W fp16 pairs [which][o][kp], Wq*QSC
__device__ float    g_bias[4 * CCH];                        // bq*QSC, bk, bv, bo

// log2(e)/sqrt(32): folded into Wq/bq so attention scores land in exp2 domain
#define QSC 0.2550348942479215f

__device__ __forceinline__ float fexp2(float z) {
    float r;
    asm("ex2.approx.f32 %0, %1;" : "=f"(r) : "f"(z));
    return r;
}
__device__ __forceinline__ uint32_t pack2(float lo, float hi) {
    uint32_t d;
    asm("cvt.rn.f16x2.f32 %0, %1, %2;" : "=r"(d) : "f"(hi), "f"(lo));
    return d;
}
__device__ __forceinline__ uint32_t prmt(uint32_t a, uint32_t b, uint32_t sel) {
    uint32_t d;
    asm("prmt.b32 %0, %1, %2, %3;" : "=r"(d) : "r"(a), "r"(b), "r"(sel));
    return d;
}
__device__ __forceinline__ void mma16(float* d, const uint32_t* a, uint32_t b0, uint32_t b1) {
    asm volatile("mma.sync.aligned.m16n8k16.row.col.f32.f16.f16.f32 "
        "{%0,%1,%2,%3}, {%4,%5,%6,%7}, {%8,%9}, {%0,%1,%2,%3};"
        : "+f"(d[0]), "+f"(d[1]), "+f"(d[2]), "+f"(d[3])
        : "r"(a[0]), "r"(a[1]), "r"(a[2]), "r"(a[3]), "r"(b0), "r"(b1));
}

// ============================================================================
// Pre-round: pack x + 4 weights into fp16 k-pair words; also stage biases.
// ============================================================================
#define NXU4 (BATCH * (CCH / 2) * NTOK / 4)   // 262144
#define NWU4 (CCH * (CCH / 2) / 4)            // 8192
#define NB   (4 * CCH)                        // 1024

__global__ void __launch_bounds__(256) preround_kernel(
    const float* __restrict__ x,
    const float* __restrict__ Wq, const float* __restrict__ Wk,
    const float* __restrict__ Wv, const float* __restrict__ Wo,
    const float* __restrict__ bq, const float* __restrict__ bk,
    const float* __restrict__ bv, const float* __restrict__ bo)
{
    int i = blockIdx.x * 256 + threadIdx.x;
    if (i < NXU4) {
        int wi = i * 4;
        int b = wi >> 17;
        int rem = wi & 131071;
        int kp = rem >> 10, n = rem & 1023;
        const float* base = x + ((size_t)b * CCH + 2 * kp) * NTOK + n;
        float4 a = *(const float4*)base;
        float4 c = *(const float4*)(base + NTOK);
        uint4 o;
        o.x = pack2(a.x, c.x); o.y = pack2(a.y, c.y);
        o.z = pack2(a.z, c.z); o.w = pack2(a.w, c.w);
        *(uint4*)(g_xh + wi) = o;
    } else if (i < NXU4 + 4 * NWU4) {
        int j = i - NXU4;
        int which = j >> 13;
        int k4 = j & (NWU4 - 1);
        int wi = k4 * 4;
        int o = wi >> 7;
        int kp = wi & 127;
        const float* W = (which == 0) ? Wq : (which == 1) ? Wk : (which == 2) ? Wv : Wo;
        float scale = (which == 0) ? QSC : 1.0f;
        const float* base = W + (size_t)o * CCH + 2 * kp;
        float4 a = *(const float4*)base;
        float4 c = *(const float4*)(base + 4);
        uint4 ov;
        ov.x = pack2(a.x * scale, a.y * scale);
        ov.y = pack2(a.z * scale, a.w * scale);
        ov.z = pack2(c.x * scale, c.y * scale);
        ov.w = pack2(c.z * scale, c.w * scale);
        *(uint4*)(g_wh + (size_t)which * 32768 + wi) = ov;
    } else {
        int j = i - NXU4 - 4 * NWU4;
        if (j < NB) {
            if (j < CCH)          g_bias[j] = bq[j] * QSC;
            else if (j < 2 * CCH) g_bias[j] = bk[j - CCH];
            else if (j < 3 * CCH) g_bias[j] = bv[j - 2 * CCH];
            else                  g_bias[j] = bo[j - 3 * CCH];
        }
    }
}

// ============================================================================
// fp16 GEMM body v2: 128 threads, block tile 64(o) x 128(n), 4 warps 2x2,
// warp tile 32x64 (identical per-warp inner loop). More CTAs -> 4/SM overlap.
// ============================================================================
#define WS 20
#define XS 132

__device__ __forceinline__ void proj_body_h16(
    const uint32_t* __restrict__ Wg, const float* __restrict__ bias,
    const uint32_t* __restrict__ Xg,
    __half* __restrict__ Yh, float* __restrict__ Yf,
    const float* __restrict__ Rb, int o0, int n0,
    uint32_t* Wsh, uint32_t* Xsh)
{
    const int t = threadIdx.x, lane = t & 31, w = t >> 5;
    const int qg = lane >> 2, p = lane & 3;
    const int r0  = (w >> 1) * 32;      // 0 / 32
    const int n0w = (w & 1) * 64;       // 0 / 64

    // staging: W 64 rows x 16 words, 2 threads/row, 8 words each
    const int so = t >> 1, sh = (t & 1) * 8;
    // X: 16 kp rows x 128 n words; thread covers rows sk+4r (r<4), one uint4
    const int sk = t >> 5, sn4 = t & 31;

    float acc[2][8][4];
    #pragma unroll
    for (int mt = 0; mt < 2; mt++)
        #pragma unroll
        for (int nt = 0; nt < 8; nt++)
            #pragma unroll
            for (int k = 0; k < 4; k++) acc[mt][nt][k] = 0.f;

    uint4 wf[2], xf[4];
    wf[0] = *(const uint4*)&Wg[(o0 + so) * 128 + sh];
    wf[1] = *(const uint4*)&Wg[(o0 + so) * 128 + sh + 4];
    #pragma unroll
    for (int r = 0; r < 4; r++)
        xf[r] = *(const uint4*)&Xg[(size_t)(sk + 4 * r) * NTOK + n0 + sn4 * 4];

    for (int k0 = 0; k0 < CCH; k0 += 32) {
        *(uint4*)&Wsh[so * WS + sh]     = wf[0];
        *(uint4*)&Wsh[so * WS + sh + 4] = wf[1];
        #pragma unroll
        for (int r = 0; r < 4; r++)
            *(uint4*)&Xsh[(sk + 4 * r) * XS + sn4 * 4] = xf[r];
        __syncthreads();

        if (k0 + 32 < CCH) {
            const int kpn = (k0 + 32) >> 1;
            wf[0] = *(const uint4*)&Wg[(o0 + so) * 128 + kpn + sh];
            wf[1] = *(const uint4*)&Wg[(o0 + so) * 128 + kpn + sh + 4];
            #pragma unroll
            for (int r = 0; r < 4; r++)
                xf[r] = *(const uint4*)&Xg[(size_t)(kpn + sk + 4 * r) * NTOK + n0 + sn4 * 4];
        }

        #pragma unroll
        for (int s = 0; s < 2; s++) {
            uint32_t a[2][4];
            #pragma unroll
            for (int mt = 0; mt < 2; mt++) {
                int rr = r0 + mt * 16 + qg;
                a[mt][0] = Wsh[rr * WS + 8 * s + p];
                a[mt][1] = Wsh[(rr + 8) * WS + 8 * s + p];
                a[mt][2] = Wsh[rr * WS + 8 * s + p + 4];
                a[mt][3] = Wsh[(rr + 8) * WS + 8 * s + p + 4];
            }
            #pragma unroll
            for (int nt = 0; nt < 8; nt++) {
                uint32_t b0 = Xsh[(8 * s + p) * XS + n0w + nt * 8 + qg];
                uint32_t b1 = Xsh[(8 * s + p + 4) * XS + n0w + nt * 8 + qg];
                mma16(acc[0][nt], a[0], b0, b1);
                mma16(acc[1][nt], a[1], b0, b1);
            }
        }
        __syncthreads();
    }

    #pragma unroll
    for (int mt = 0; mt < 2; mt++) {
        int rr = r0 + mt * 16 + qg;
        int oa = o0 + rr;
        float bb0 = bias[oa], bb8 = bias[oa + 8];
        #pragma unroll
        for (int nt = 0; nt < 8; nt++) {
            int col = n0 + n0w + nt * 8 + 2 * p;
            size_t i0 = (size_t)oa * NTOK + col;
            size_t i8 = (size_t)(oa + 8) * NTOK + col;
            float2 v0 = make_float2(acc[mt][nt][0] + bb0, acc[mt][nt][1] + bb0);
            float2 v8 = make_float2(acc[mt][nt][2] + bb8, acc[mt][nt][3] + bb8);
            if (Yh) {
                *(uint32_t*)&Yh[i0] = pack2(v0.x, v0.y);
                *(uint32_t*)&Yh[i8] = pack2(v8.x, v8.y);
            } else {
                float2 r0v = *(const float2*)&Rb[i0];
                float2 r8v = *(const float2*)&Rb[i8];
                v0.x += r0v.x; v0.y += r0v.y;
                v8.x += r8v.x; v8.y += r8v.y;
                *(float2*)&Yf[i0] = v0;
                *(float2*)&Yf[i8] = v8;
            }
        }
    }
}

// Fused Q/K/V projection: grid.y in [0,12) = which*4 + o-tile(64). fp16 out.
__global__ void __launch_bounds__(128, 4) qkv_mma_kernel()
{
    __shared__ uint32_t Wsh[64 * WS];
    __shared__ uint32_t Xsh[16 * XS];

    const int b     = blockIdx.z;
    const int which = blockIdx.y >> 2;
    const int o0    = (blockIdx.y & 3) * 64;
    const int n0    = blockIdx.x * 128;

    const uint32_t* Wg = g_wh + (size_t)which * 32768;
    const uint32_t* Xg = g_xh + (size_t)b * 128 * NTOK;
    __half* Yh = g_qkvh + ((size_t)which * BATCH + b) * CCH * NTOK;

    proj_body_h16(Wg, g_bias + which * CCH, Xg, Yh, nullptr, nullptr, o0, n0, Wsh, Xsh);
}

// Output projection (+residual): grid.y in [0,4) = o-tile(64). fp32 out.
__global__ void __launch_bounds__(128, 4) oproj_mma_kernel(
    float* __restrict__ out, const float* __restrict__ x)
{
    __shared__ uint32_t Wsh[64 * WS];
    __shared__ uint32_t Xsh[16 * XS];

    const int b  = blockIdx.z;
    const int o0 = blockIdx.y * 64;
    const int n0 = blockIdx.x * 128;

    const uint32_t* Wg = g_wh + 3ull * 32768;
    const uint32_t* Xg = g_oh + (size_t)b * 128 * NTOK;
    const float* Rb = x + (size_t)b * CCH * NTOK;
    float* Yf = out + (size_t)b * CCH * NTOK;

    proj_body_h16(Wg, g_bias + 3 * CCH, Xg, nullptr, Yf, Rb, o0, n0, Wsh, Xsh);
}

// ============================================================================
// Attention v8 (unchanged from Round 16): 64-key chunks, ones-column rowsum
// MMA, fp16 m16n8k16, MUFU exp2, packed fp16 O output.
// ============================================================================
#define KWRD(row, w) (4 * (row) + ((w) & 3) + ((w) >> 2) * 260)
#define KWORDS 1036
#define VWORDS 1948

__global__ void __launch_bounds__(128, 4) attn_mma_kernel()
{
    __shared__ uint32_t Ku[2][KWORDS];
    __shared__ uint32_t Vu[2][VWORDS];

    const int t = threadIdx.x, w = t >> 5, lane = t & 31;
    const int qg = lane >> 2, p = lane & 3;
    const int b = blockIdx.z, h = blockIdx.y, q0 = blockIdx.x * 128;

    const size_t ho = ((size_t)b * CCH + h * HD) * NTOK;
    const uint16_t* Q16 = (const uint16_t*)(g_qkvh + ho);
    const uint32_t* KuG = (const uint32_t*)(g_qkvh + (size_t)BATCH * CCH * NTOK + ho);
    const uint32_t* VuG = (const uint32_t*)(g_qkvh + 2ull * BATCH * CCH * NTOK + ho);
    uint32_t* Oh = g_oh + ((size_t)b * 128 + h * 16) * NTOK;

    const int rbase = q0 + w * 32 + qg;
    uint32_t aq[2][2][4];
    #pragma unroll
    for (int mt = 0; mt < 2; mt++)
        #pragma unroll
        for (int s = 0; s < 2; s++) {
            int i = rbase + mt * 16;
            int d = 16 * s + 2 * p;
            aq[mt][s][0] = (uint32_t)Q16[d * NTOK + i]           | ((uint32_t)Q16[(d + 1) * NTOK + i] << 16);
            aq[mt][s][1] = (uint32_t)Q16[d * NTOK + i + 8]       | ((uint32_t)Q16[(d + 1) * NTOK + i + 8] << 16);
            aq[mt][s][2] = (uint32_t)Q16[(d + 8) * NTOK + i]     | ((uint32_t)Q16[(d + 9) * NTOK + i] << 16);
            aq[mt][s][3] = (uint32_t)Q16[(d + 8) * NTOK + i + 8] | ((uint32_t)Q16[(d + 9) * NTOK + i + 8] << 16);
        }

    float oc[2][4][4];
    #pragma unroll
    for (int mt = 0; mt < 2; mt++)
        #pragma unroll
        for (int nt = 0; nt < 4; nt++)
            #pragma unroll
            for (int k = 0; k < 4; k++) oc[mt][nt][k] = 0.f;
    float accS[2][4] = {{0.f, 0.f, 0.f, 0.f}, {0.f, 0.f, 0.f, 0.f}};

    const uint32_t oneb = (qg == 0) ? 0x3C003C00u : 0u;

    const int j2  = (t & 3) + 4 * (t >> 5);
    const int w0b = (t >> 2) & 7;
    const int dvv = (t & 7) + 8 * ((t >> 5) & 3);
    const int wvb = (t >> 3) & 3;

    uint32_t kp[2][2][2], vp[2][4];
    #pragma unroll
    for (int hh = 0; hh < 2; hh++) {
        #pragma unroll
        for (int it = 0; it < 2; it++) {
            int w0 = w0b + 8 * it;
            kp[hh][it][0] = KuG[1024 * w0 + 16 * hh + j2];
            kp[hh][it][1] = KuG[1024 * w0 + 512 + 16 * hh + j2];
        }
        #pragma unroll
        for (int it = 0; it < 4; it++)
            vp[hh][it] = VuG[dvv * 512 + 16 * hh + wvb + 4 * it];
    }

    for (int c = 0; c < 16; c++) {
        uint32_t* Kc = Ku[c & 1];
        uint32_t* Vc = Vu[c & 1];

        #pragma unroll
        for (int hh = 0; hh < 2; hh++) {
            #pragma unroll
            for (int it = 0; it < 2; it++) {
                int w0 = w0b + 8 * it;
                int row = 2 * j2 + 32 * hh;
                Kc[KWRD(row, w0)]     = prmt(kp[hh][it][0], kp[hh][it][1], 0x5410);
                Kc[KWRD(row + 1, w0)] = prmt(kp[hh][it][0], kp[hh][it][1], 0x7632);
            }
            #pragma unroll
            for (int it = 0; it < 4; it++)
                Vc[KWRD(dvv, wvb + 4 * it + 16 * hh)] = vp[hh][it];
        }
        __syncthreads();

        if (c < 15) {
            const int ktw = (c + 1) * 32;
            #pragma unroll
            for (int hh = 0; hh < 2; hh++) {
                #pragma unroll
                for (int it = 0; it < 2; it++) {
                    int w0 = w0b + 8 * it;
                    kp[hh][it][0] = KuG[1024 * w0 + ktw + 16 * hh + j2];
                    kp[hh][it][1] = KuG[1024 * w0 + 512 + ktw + 16 * hh + j2];
                }
                #pragma unroll
                for (int it = 0; it < 4; it++)
                    vp[hh][it] = VuG[dvv * 512 + ktw + 16 * hh + wvb + 4 * it];
            }
        }

        #pragma unroll
        for (int hh = 0; hh < 2; hh++) {
            float sc[2][4][4];
            #pragma unroll
            for (int mt = 0; mt < 2; mt++)
                #pragma unroll
                for (int nt = 0; nt < 4; nt++)
                    #pragma unroll
                    for (int k = 0; k < 4; k++) sc[mt][nt][k] = 0.f;

            #pragma unroll
            for (int s = 0; s < 2; s++)
                #pragma unroll
                for (int nt = 0; nt < 4; nt++) {
                    int row = 32 * hh + nt * 8 + qg;
                    uint32_t b0 = Kc[KWRD(row, 8 * s + p)];
                    uint32_t b1 = Kc[KWRD(row, 8 * s + p + 4)];
                    mma16(sc[0][nt], aq[0][s], b0, b1);
                    mma16(sc[1][nt], aq[1][s], b0, b1);
                }

            #pragma unroll
            for (int mt = 0; mt < 2; mt++)
                #pragma unroll
                for (int nt = 0; nt < 4; nt++) {
                    sc[mt][nt][0] = fexp2(sc[mt][nt][0]);
                    sc[mt][nt][1] = fexp2(sc[mt][nt][1]);
                    sc[mt][nt][2] = fexp2(sc[mt][nt][2]);
                    sc[mt][nt][3] = fexp2(sc[mt][nt][3]);
                }

            #pragma unroll
            for (int s = 0; s < 2; s++) {
                uint32_t ap[2][4];
                #pragma unroll
                for (int mt = 0; mt < 2; mt++) {
                    ap[mt][0] = pack2(sc[mt][2 * s][0],     sc[mt][2 * s][1]);
                    ap[mt][1] = pack2(sc[mt][2 * s][2],     sc[mt][2 * s][3]);
                    ap[mt][2] = pack2(sc[mt][2 * s + 1][0], sc[mt][2 * s + 1][1]);
                    ap[mt][3] = pack2(sc[mt][2 * s + 1][2], sc[mt][2 * s + 1][3]);
                }
                mma16(accS[0], ap[0], oneb, oneb);
                mma16(accS[1], ap[1], oneb, oneb);
                #pragma unroll
                for (int nt = 0; nt < 4; nt++) {
                    int vw = 16 * hh + 8 * s + p;
                    uint32_t b0 = Vc[KWRD(nt * 8 + qg, vw)];
                    uint32_t b1 = Vc[KWRD(nt * 8 + qg, vw + 4)];
                    mma16(oc[0][nt], ap[0], b0, b1);
                    mma16(oc[1][nt], ap[1], b0, b1);
                }
            }
        }
    }

    #pragma unroll
    for (int mt = 0; mt < 2; mt++) {
        float s0 = __shfl_sync(0xffffffffu, accS[mt][0], lane & ~3);
        float s1 = __shfl_sync(0xffffffffu, accS[mt][2], lane & ~3);
        float r0i = 1.0f / s0, r1i = 1.0f / s1;
        int r = rbase + mt * 16;
        #pragma unroll
        for (int nt = 0; nt < 4; nt++) {
            uint32_t* row = Oh + (size_t)(nt * 4 + p) * NTOK;
            row[r]     = pack2(oc[mt][nt][0] * r0i, oc[mt][nt][1] * r0i);
            row[r + 8] = pack2(oc[mt][nt][2] * r1i, oc[mt][nt][3] * r1i);
        }
    }
}

// ============================================================================
extern "C" void kernel_launch(void* const* d_in, const int* in_sizes, int n_in,
                              void* d_out, int out_size)
{
    const float* x  = (const float*)d_in[0];
    const float* Wq = (const float*)d_in[1];
    const float* bq = (const float*)d_in[2];
    const float* Wk = (const float*)d_in[3];
    const float* bk = (const float*)d_in[4];
    const float* Wv = (const float*)d_in[5];
    const float* bv = (const float*)d_in[6];
    const float* Wo = (const float*)d_in[7];
    const float* bo = (const float*)d_in[8];
    float* out = (float*)d_out;

    preround_kernel<<<(NXU4 + 4 * NWU4 + NB + 255) / 256, 256>>>(
        x, Wq, Wk, Wv, Wo, bq, bk, bv, bo);

    qkv_mma_kernel<<<dim3(NTOK / 128, 12, BATCH), 128>>>();
    attn_mma_kernel<<<dim3(NTOK / 128, HEADS, BATCH), 128>>>();
    oproj_mma_kernel<<<dim3(NTOK / 128, CCH / 64, BATCH), 128>>>(out, x);
}